// round 3
// baseline (speedup 1.0000x reference)
#include <cuda_runtime.h>
#include <math.h>

#define N_TOK  4096
#define DMODEL 1024
#define HEADS  16
#define DH     64

// ---- scratch (no allocations allowed) ----
__device__ float g_Q[N_TOK * DMODEL];
__device__ float g_K[N_TOK * DMODEL];
__device__ float g_V[N_TOK * DMODEL];
__device__ float g_O[N_TOK * DMODEL];

// ============================================================================
// SGEMM: C[M,N] = A[M,K] @ B[K,N], row-major, M%128==0, N%128==0, K%8==0.
// 128x128 block tile, K-tile 8, 256 threads, 8x8 per-thread microtile.
// ============================================================================
__global__ __launch_bounds__(256) void sgemm128(
    const float* __restrict__ A, const float* __restrict__ B,
    float* __restrict__ C, int M, int N, int K)
{
    __shared__ float As[8][128];   // [k][m] (transposed on store)
    __shared__ float Bs[8][128];   // [k][n]

    const int tx = threadIdx.x, ty = threadIdx.y;
    const int tid = ty * 16 + tx;
    const int m0 = blockIdx.y * 128, n0 = blockIdx.x * 128;

    const int arow = tid >> 1;          // 0..127
    const int akq  = (tid & 1) * 4;     // 0 or 4
    const int brow = tid >> 5;          // 0..7
    const int bc   = (tid & 31) * 4;    // 0..124

    const float* Ap = A + (size_t)(m0 + arow) * K + akq;
    const float* Bp = B + (size_t)brow * N + n0 + bc;

    float acc[8][8];
#pragma unroll
    for (int i = 0; i < 8; i++)
#pragma unroll
        for (int j = 0; j < 8; j++) acc[i][j] = 0.0f;

    for (int k0 = 0; k0 < K; k0 += 8) {
        float4 av = *(const float4*)Ap;
        float4 bv = *(const float4*)Bp;
        As[akq + 0][arow] = av.x;
        As[akq + 1][arow] = av.y;
        As[akq + 2][arow] = av.z;
        As[akq + 3][arow] = av.w;
        *(float4*)&Bs[brow][bc] = bv;
        __syncthreads();

#pragma unroll
        for (int k = 0; k < 8; k++) {
            float ra[8], rb[8];
            *(float4*)&ra[0] = *(const float4*)&As[k][ty * 4];
            *(float4*)&ra[4] = *(const float4*)&As[k][64 + ty * 4];
            *(float4*)&rb[0] = *(const float4*)&Bs[k][tx * 4];
            *(float4*)&rb[4] = *(const float4*)&Bs[k][64 + tx * 4];
#pragma unroll
            for (int i = 0; i < 8; i++)
#pragma unroll
                for (int j = 0; j < 8; j++)
                    acc[i][j] += ra[i] * rb[j];
        }
        __syncthreads();
        Ap += 8;
        Bp += (size_t)8 * N;
    }

#pragma unroll
    for (int i = 0; i < 8; i++) {
        int row = m0 + ((i < 4) ? (ty * 4 + i) : (64 + ty * 4 + (i - 4)));
        *(float4*)&C[(size_t)row * N + n0 + tx * 4] =
            make_float4(acc[i][0], acc[i][1], acc[i][2], acc[i][3]);
        *(float4*)&C[(size_t)row * N + n0 + 64 + tx * 4] =
            make_float4(acc[i][4], acc[i][5], acc[i][6], acc[i][7]);
    }
}

// ============================================================================
// L2-normalize each (token, head) slice of length DH=64, times `scale`.
// One warp per slice.
// ============================================================================
__global__ __launch_bounds__(256) void l2norm_kernel(float* __restrict__ X, float scale)
{
    int warp = (blockIdx.x * blockDim.x + threadIdx.x) >> 5;
    int lane = threadIdx.x & 31;
    if (warp >= N_TOK * HEADS) return;
    float* p = X + (size_t)(warp / HEADS) * DMODEL + (warp % HEADS) * DH;
    float a = p[lane];
    float b = p[lane + 32];
    float ss = a * a + b * b;
#pragma unroll
    for (int off = 16; off > 0; off >>= 1)
        ss += __shfl_xor_sync(0xffffffffu, ss, off);
    float inv = scale / fmaxf(sqrtf(ss), 1e-12f);
    p[lane]      = a * inv;
    p[lane + 32] = b * inv;
}

// ============================================================================
// Flash-attention (causal), fp32. Per block: 64 queries of one head.
// Q,K,V,O in [n, d] layout (head slice at column head*64).
// 256 threads (16x16), 4x4 microtiles.  Online softmax.
// KPs buffer is reused: K-tile [c][j] during S=QK^T, then P [i][j] during PV.
// ============================================================================
__global__ __launch_bounds__(256) void flash_attn(
    const float* __restrict__ Q, const float* __restrict__ K,
    const float* __restrict__ V, float* __restrict__ O)
{
    __shared__ float Qs[DH][64];    // [c][i]   (transposed)
    __shared__ float KPs[64][64];   // phase 1: K [c][j]; phase 2: P [i][j]
    __shared__ float Vs[64][64];    // [j][c]

    const int tx = threadIdx.x, ty = threadIdx.y;
    const int tid  = ty * 16 + tx;
    const int head = blockIdx.y;
    const int qs   = blockIdx.x * 64;
    const int hoff = head * DH;

    // load Q tile (transposed into smem)
#pragma unroll
    for (int it = 0; it < 4; it++) {
        int e   = tid + it * 256;
        int row = e >> 4;
        int c4  = (e & 15) << 2;
        float4 v = *(const float4*)&Q[(size_t)(qs + row) * DMODEL + hoff + c4];
        Qs[c4 + 0][row] = v.x;
        Qs[c4 + 1][row] = v.y;
        Qs[c4 + 2][row] = v.z;
        Qs[c4 + 3][row] = v.w;
    }

    float m[4], l[4], o[4][4];
#pragma unroll
    for (int r = 0; r < 4; r++) {
        m[r] = -3.0e38f;
        l[r] = 0.0f;
#pragma unroll
        for (int c = 0; c < 4; c++) o[r][c] = 0.0f;
    }

    const int nkb = blockIdx.x;  // key blocks 0..nkb inclusive
    for (int kb = 0; kb <= nkb; kb++) {
        const int ks = kb * 64;
        __syncthreads();  // prev PV done (and Qs stores on first iter)

        // load K (transposed) and V tiles
#pragma unroll
        for (int it = 0; it < 4; it++) {
            int e   = tid + it * 256;
            int row = e >> 4;
            int c4  = (e & 15) << 2;
            float4 kv = *(const float4*)&K[(size_t)(ks + row) * DMODEL + hoff + c4];
            KPs[c4 + 0][row] = kv.x;
            KPs[c4 + 1][row] = kv.y;
            KPs[c4 + 2][row] = kv.z;
            KPs[c4 + 3][row] = kv.w;
            float4 vv = *(const float4*)&V[(size_t)(ks + row) * DMODEL + hoff + c4];
            *(float4*)&Vs[row][c4] = vv;
        }
        __syncthreads();

        // S = Q K^T   (scale folded into Q)
        float s[4][4];
#pragma unroll
        for (int r = 0; r < 4; r++)
#pragma unroll
            for (int c = 0; c < 4; c++) s[r][c] = 0.0f;
#pragma unroll
        for (int c = 0; c < DH; c++) {
            float4 q4 = *(const float4*)&Qs[c][ty * 4];
            float4 k4 = *(const float4*)&KPs[c][tx * 4];
            float rq[4] = {q4.x, q4.y, q4.z, q4.w};
            float rk[4] = {k4.x, k4.y, k4.z, k4.w};
#pragma unroll
            for (int r = 0; r < 4; r++)
#pragma unroll
                for (int cc = 0; cc < 4; cc++)
                    s[r][cc] += rq[r] * rk[cc];
        }

        // causal mask on diagonal block
        if (kb == nkb) {
#pragma unroll
            for (int r = 0; r < 4; r++)
#pragma unroll
                for (int cc = 0; cc < 4; cc++)
                    if (ks + tx * 4 + cc > qs + ty * 4 + r)
                        s[r][cc] = -3.0e38f;
        }

        // online softmax update (row groups of 16 lanes; xor<=8 stays in group)
#pragma unroll
        for (int r = 0; r < 4; r++) {
            float mx = fmaxf(fmaxf(s[r][0], s[r][1]), fmaxf(s[r][2], s[r][3]));
#pragma unroll
            for (int off = 8; off > 0; off >>= 1)
                mx = fmaxf(mx, __shfl_xor_sync(0xffffffffu, mx, off));
            float mnew  = fmaxf(m[r], mx);
            float alpha = __expf(m[r] - mnew);
            m[r] = mnew;
            float rs = 0.0f;
#pragma unroll
            for (int cc = 0; cc < 4; cc++) {
                s[r][cc] = __expf(s[r][cc] - mnew);
                rs += s[r][cc];
            }
#pragma unroll
            for (int off = 8; off > 0; off >>= 1)
                rs += __shfl_xor_sync(0xffffffffu, rs, off);
            l[r] = l[r] * alpha + rs;
#pragma unroll
            for (int cc = 0; cc < 4; cc++) o[r][cc] *= alpha;
        }

        __syncthreads();  // all S reads of KPs done before overwrite with P
#pragma unroll
        for (int r = 0; r < 4; r++)
#pragma unroll
            for (int cc = 0; cc < 4; cc++)
                KPs[ty * 4 + r][tx * 4 + cc] = s[r][cc];
        __syncthreads();

        // O += P @ V
#pragma unroll 8
        for (int j = 0; j < 64; j++) {
            float4 v4 = *(const float4*)&Vs[j][tx * 4];
#pragma unroll
            for (int r = 0; r < 4; r++) {
                float p = KPs[ty * 4 + r][j];
                o[r][0] += p * v4.x;
                o[r][1] += p * v4.y;
                o[r][2] += p * v4.z;
                o[r][3] += p * v4.w;
            }
        }
    }

    // epilogue: divide by l, store
#pragma unroll
    for (int r = 0; r < 4; r++) {
        float inv = 1.0f / l[r];
        *(float4*)&O[(size_t)(qs + ty * 4 + r) * DMODEL + hoff + tx * 4] =
            make_float4(o[r][0] * inv, o[r][1] * inv, o[r][2] * inv, o[r][3] * inv);
    }
}

// ============================================================================
extern "C" void kernel_launch(void* const* d_in, const int* in_sizes, int n_in,
                              void* d_out, int out_size)
{
    const float* x  = (const float*)d_in[0];
    const float* Wq = (const float*)d_in[1];
    const float* Wk = (const float*)d_in[2];
    const float* Wv = (const float*)d_in[3];
    const float* Wo = (const float*)d_in[4];
    float* out = (float*)d_out;

    float *Qp, *Kp, *Vp, *Op;
    cudaGetSymbolAddress((void**)&Qp, g_Q);
    cudaGetSymbolAddress((void**)&Kp, g_K);
    cudaGetSymbolAddress((void**)&Vp, g_V);
    cudaGetSymbolAddress((void**)&Op, g_O);

    dim3 blk(16, 16);
    dim3 gemm_grid(DMODEL / 128, N_TOK / 128);   // (8, 32)

    sgemm128<<<gemm_grid, blk>>>(x, Wq, Qp, N_TOK, DMODEL, DMODEL);
    sgemm128<<<gemm_grid, blk>>>(x, Wk, Kp, N_TOK, DMODEL, DMODEL);
    sgemm128<<<gemm_grid, blk>>>(x, Wv, Vp, N_TOK, DMODEL, DMODEL);

    int norm_blocks = (N_TOK * HEADS) / 8;       // 8 warps per block
    l2norm_kernel<<<norm_blocks, 256>>>(Qp, 8.0f);   // SCALE folded into Q
    l2norm_kernel<<<norm_blocks, 256>>>(Kp, 1.0f);

    dim3 fa_grid(N_TOK / 64, HEADS);             // (64, 16)
    flash_attn<<<fa_grid, blk>>>(Qp, Kp, Vp, Op);

    sgemm128<<<gemm_grid, blk>>>(Op, Wo, out, N_TOK, DMODEL, DMODEL);
}

// round 8
// speedup vs baseline: 1.2634x; 1.2634x over previous
#include <cuda_runtime.h>
#include <cuda_bf16.h>
#include <math.h>
#include <stdint.h>

#define N_TOK  4096
#define DMODEL 1024
#define HEADS  16
#define DH     64

// ---- scratch (no allocations allowed) ----
__device__ float g_Q[N_TOK * DMODEL];
__device__ float g_K[N_TOK * DMODEL];
__device__ float g_V[N_TOK * DMODEL];
__device__ float g_O[N_TOK * DMODEL];
__device__ __nv_bfloat16 g_xhi[N_TOK * DMODEL];
__device__ __nv_bfloat16 g_xlo[N_TOK * DMODEL];
__device__ __nv_bfloat16 g_Ohi[N_TOK * DMODEL];
__device__ __nv_bfloat16 g_Olo[N_TOK * DMODEL];
__device__ __nv_bfloat16 g_Wthi[4][DMODEL * DMODEL];   // W^T, bf16 hi
__device__ __nv_bfloat16 g_Wtlo[4][DMODEL * DMODEL];   // W^T, bf16 lo

// ============================================================================
// Base-ISA helpers (NO tcgen05 — ptxas here targets plain sm_103)
// ============================================================================
static __device__ __forceinline__ uint32_t smem_u32(const void* p) {
    uint32_t a;
    asm("{ .reg .u64 t; cvta.to.shared.u64 t, %1; cvt.u32.u64 %0, t; }"
        : "=r"(a) : "l"(p));
    return a;
}
static __device__ __forceinline__ void cp_async16(uint32_t saddr, const void* gaddr) {
    asm volatile("cp.async.cg.shared.global [%0], [%1], 16;"
                 :: "r"(saddr), "l"(gaddr) : "memory");
}
#define CP_COMMIT() asm volatile("cp.async.commit_group;" ::: "memory")
#define CP_WAIT(n)  asm volatile("cp.async.wait_group %0;" :: "n"(n) : "memory")

static __device__ __forceinline__ void ldsm_x4(uint32_t* r, uint32_t addr) {
    asm volatile("ldmatrix.sync.aligned.m8n8.x4.shared.b16 {%0,%1,%2,%3}, [%4];"
                 : "=r"(r[0]), "=r"(r[1]), "=r"(r[2]), "=r"(r[3]) : "r"(addr));
}
static __device__ __forceinline__ void mma_bf16(float* d, const uint32_t* a,
                                                uint32_t b0, uint32_t b1) {
    asm volatile(
        "mma.sync.aligned.m16n8k16.row.col.f32.bf16.bf16.f32 "
        "{%0,%1,%2,%3}, {%4,%5,%6,%7}, {%8,%9}, {%0,%1,%2,%3};"
        : "+f"(d[0]), "+f"(d[1]), "+f"(d[2]), "+f"(d[3])
        : "r"(a[0]), "r"(a[1]), "r"(a[2]), "r"(a[3]), "r"(b0), "r"(b1));
}

// ============================================================================
// Pre-pass: split fp32 -> bf16 hi/lo (row-preserving)
// ============================================================================
__global__ __launch_bounds__(256) void split_rows(
    const float* __restrict__ in, __nv_bfloat16* __restrict__ hi,
    __nv_bfloat16* __restrict__ lo, int n4)
{
    int i = blockIdx.x * 256 + threadIdx.x;
    if (i >= n4) return;
    float4 v = ((const float4*)in)[i];
    float a[4] = {v.x, v.y, v.z, v.w};
    __nv_bfloat16 h[4], l[4];
#pragma unroll
    for (int j = 0; j < 4; j++) {
        h[j] = __float2bfloat16(a[j]);
        l[j] = __float2bfloat16(a[j] - __bfloat162float(h[j]));
    }
    __nv_bfloat162* hp = (__nv_bfloat162*)(hi + (size_t)i * 4);
    __nv_bfloat162* lp = (__nv_bfloat162*)(lo + (size_t)i * 4);
    hp[0] = __nv_bfloat162(h[0], h[1]);
    hp[1] = __nv_bfloat162(h[2], h[3]);
    lp[0] = __nv_bfloat162(l[0], l[1]);
    lp[1] = __nv_bfloat162(l[2], l[3]);
}

// ============================================================================
// Pre-pass: W [K,N] fp32 -> W^T [N,K] bf16 hi/lo (tiled transpose)
// ============================================================================
__global__ __launch_bounds__(256) void split_transpose(
    const float* __restrict__ W, __nv_bfloat16* __restrict__ Thi,
    __nv_bfloat16* __restrict__ Tlo)
{
    __shared__ float ts[32][33];
    int tx = threadIdx.x, ty = threadIdx.y;   // 32 x 8
    int x = blockIdx.x * 32 + tx;
#pragma unroll
    for (int i = 0; i < 4; i++)
        ts[ty + i * 8][tx] = W[(size_t)(blockIdx.y * 32 + ty + i * 8) * DMODEL + x];
    __syncthreads();
    int ox = blockIdx.y * 32 + tx;
#pragma unroll
    for (int i = 0; i < 4; i++) {
        float a = ts[tx][ty + i * 8];
        __nv_bfloat16 h = __float2bfloat16(a);
        size_t idx = (size_t)(blockIdx.x * 32 + ty + i * 8) * DMODEL + ox;
        Thi[idx] = h;
        Tlo[idx] = __float2bfloat16(a - __bfloat162float(h));
    }
}

// ============================================================================
// Tensor-core GEMM via mma.sync (base ISA): C[M,N] = A @ B^T
// A=[M,K] bf16 hi/lo (K-major), B=[N,K] bf16 hi/lo (pre-transposed, K-major)
// 3-term error-compensated split.  CTA tile 128x128, 8 warps (2x4),
// warp tile 64x32, K-chunk 32, cp.async double buffering.
// Row pad to 40 bf16 (80B) -> ldmatrix conflict-free.
// ============================================================================
#define KC 32
#define KP 40
#define TB (128 * KP * 2)              // bytes per tensor tile: 10240
#define OFF_AH 0
#define OFF_AL (TB)
#define OFF_BH (2 * TB)
#define OFF_BL (3 * TB)
#define STAGE_B (4 * TB)               // 40960
#define GEMM_SMEM (2 * STAGE_B)        // 81920

__global__ __launch_bounds__(256) void gemm_tc(
    const __nv_bfloat16* __restrict__ Ahi, const __nv_bfloat16* __restrict__ Alo,
    const __nv_bfloat16* __restrict__ Bhi, const __nv_bfloat16* __restrict__ Blo,
    float* __restrict__ C)
{
    extern __shared__ char smem[];
    const uint32_t sbase = smem_u32(smem);
    const int tid  = threadIdx.x;
    const int lane = tid & 31, warp = tid >> 5;
    const int wm = warp >> 2, wn = warp & 3;          // 2 x 4 warp grid
    const int m0 = blockIdx.y * 128, n0 = blockIdx.x * 128;

    // global loader coords: 2 x 16B segs per tensor per thread
    const int lrow0 = tid >> 1;                       // 0..127  (seg pair base)
    const int lsg0  = (tid & 1) * 2;                  // 0 or 2

    float acc[4][4][4];
#pragma unroll
    for (int i = 0; i < 4; i++)
#pragma unroll
        for (int j = 0; j < 4; j++)
#pragma unroll
            for (int r = 0; r < 4; r++) acc[i][j][r] = 0.0f;

    const int NSTG = DMODEL / KC;                     // 32

    // ---- issue stage 0 loads ----
#pragma unroll
    for (int q = 0; q < 2; q++) {
        int sg = lsg0 + q;
        uint32_t so = (uint32_t)(lrow0 * KP * 2 + sg * 16);
        size_t ga = (size_t)(m0 + lrow0) * DMODEL + sg * 8;
        size_t gb = (size_t)(n0 + lrow0) * DMODEL + sg * 8;
        cp_async16(sbase + OFF_AH + so, Ahi + ga);
        cp_async16(sbase + OFF_AL + so, Alo + ga);
        cp_async16(sbase + OFF_BH + so, Bhi + gb);
        cp_async16(sbase + OFF_BL + so, Blo + gb);
    }
    CP_COMMIT();

    // ldmatrix lane mapping (byte offsets within a tensor tile)
    const uint32_t a_r = (uint32_t)((lane & 15));
    const uint32_t a_c = (uint32_t)(((lane >> 4) << 3));
    const uint32_t b_r = (uint32_t)((lane & 7) + ((lane >> 4) << 3));
    const uint32_t b_c = (uint32_t)((((lane >> 3) & 1) << 3));

    for (int s = 0; s < NSTG; s++) {
        if (s + 1 < NSTG) {
            const int k0 = (s + 1) * KC;
            const uint32_t bb = sbase + ((s + 1) & 1) * STAGE_B;
#pragma unroll
            for (int q = 0; q < 2; q++) {
                int sg = lsg0 + q;
                uint32_t so = (uint32_t)(lrow0 * KP * 2 + sg * 16);
                size_t ga = (size_t)(m0 + lrow0) * DMODEL + k0 + sg * 8;
                size_t gb = (size_t)(n0 + lrow0) * DMODEL + k0 + sg * 8;
                cp_async16(bb + OFF_AH + so, Ahi + ga);
                cp_async16(bb + OFF_AL + so, Alo + ga);
                cp_async16(bb + OFF_BH + so, Bhi + gb);
                cp_async16(bb + OFF_BL + so, Blo + gb);
            }
            CP_COMMIT();
            CP_WAIT(1);
        } else {
            CP_WAIT(0);
        }
        __syncthreads();

        const uint32_t bb = sbase + (s & 1) * STAGE_B;
#pragma unroll
        for (int ks = 0; ks < 2; ks++) {
            uint32_t ah[4][4], al[4][4], bh[2][4], bl[2][4];
            const uint32_t acol = (uint32_t)(ks * 16) + a_c;
            const uint32_t bcol = (uint32_t)(ks * 16) + b_c;
#pragma unroll
            for (int i = 0; i < 4; i++) {
                uint32_t off = ((uint32_t)(wm * 64 + i * 16) + a_r) * (KP * 2) + acol * 2;
                ldsm_x4(ah[i], bb + OFF_AH + off);
                ldsm_x4(al[i], bb + OFF_AL + off);
            }
#pragma unroll
            for (int j2 = 0; j2 < 2; j2++) {
                uint32_t off = ((uint32_t)(wn * 32 + j2 * 16) + b_r) * (KP * 2) + bcol * 2;
                ldsm_x4(bh[j2], bb + OFF_BH + off);
                ldsm_x4(bl[j2], bb + OFF_BL + off);
            }
#pragma unroll
            for (int i = 0; i < 4; i++)
#pragma unroll
                for (int j = 0; j < 4; j++) {
                    int j2 = j >> 1, jr = (j & 1) * 2;
                    mma_bf16(acc[i][j], ah[i], bh[j2][jr], bh[j2][jr + 1]);
                    mma_bf16(acc[i][j], ah[i], bl[j2][jr], bl[j2][jr + 1]);
                    mma_bf16(acc[i][j], al[i], bh[j2][jr], bh[j2][jr + 1]);
                }
        }
        __syncthreads();
    }

    // ---- epilogue ----
    const int gq = lane >> 2, tq = lane & 3;
#pragma unroll
    for (int i = 0; i < 4; i++) {
        int row = m0 + wm * 64 + i * 16 + gq;
#pragma unroll
        for (int j = 0; j < 4; j++) {
            int col = n0 + wn * 32 + j * 8 + tq * 2;
            *(float2*)&C[(size_t)row * DMODEL + col] =
                make_float2(acc[i][j][0], acc[i][j][1]);
            *(float2*)&C[(size_t)(row + 8) * DMODEL + col] =
                make_float2(acc[i][j][2], acc[i][j][3]);
        }
    }
}

// ============================================================================
// L2-normalize each (token, head) slice of length DH=64, times `scale`.
// ============================================================================
__global__ __launch_bounds__(256) void l2norm_kernel(float* __restrict__ X, float scale)
{
    int warp = (blockIdx.x * blockDim.x + threadIdx.x) >> 5;
    int lane = threadIdx.x & 31;
    if (warp >= N_TOK * HEADS) return;
    float* p = X + (size_t)(warp / HEADS) * DMODEL + (warp % HEADS) * DH;
    float a = p[lane];
    float b = p[lane + 32];
    float ss = a * a + b * b;
#pragma unroll
    for (int off = 16; off > 0; off >>= 1)
        ss += __shfl_xor_sync(0xffffffffu, ss, off);
    float inv = scale / fmaxf(sqrtf(ss), 1e-12f);
    p[lane]      = a * inv;
    p[lane + 32] = b * inv;
}

// ============================================================================
// Flash-attention (causal), fp32. Per block: 64 queries of one head.
// Block-index reversed so heaviest CTAs launch first.
// ============================================================================
__global__ __launch_bounds__(256) void flash_attn(
    const float* __restrict__ Q, const float* __restrict__ K,
    const float* __restrict__ V, float* __restrict__ O)
{
    __shared__ float Qs[DH][64];
    __shared__ float KPs[64][64];
    __shared__ float Vs[64][64];

    const int tx = threadIdx.x, ty = threadIdx.y;
    const int tid  = ty * 16 + tx;
    const int head = blockIdx.y;
    const int qi   = gridDim.x - 1 - blockIdx.x;   // heavy blocks first
    const int qs   = qi * 64;
    const int hoff = head * DH;

#pragma unroll
    for (int it = 0; it < 4; it++) {
        int e   = tid + it * 256;
        int row = e >> 4;
        int c4  = (e & 15) << 2;
        float4 v = *(const float4*)&Q[(size_t)(qs + row) * DMODEL + hoff + c4];
        Qs[c4 + 0][row] = v.x;
        Qs[c4 + 1][row] = v.y;
        Qs[c4 + 2][row] = v.z;
        Qs[c4 + 3][row] = v.w;
    }

    float m[4], l[4], o[4][4];
#pragma unroll
    for (int r = 0; r < 4; r++) {
        m[r] = -3.0e38f;
        l[r] = 0.0f;
#pragma unroll
        for (int c = 0; c < 4; c++) o[r][c] = 0.0f;
    }

    const int nkb = qi;
    for (int kb = 0; kb <= nkb; kb++) {
        const int ks = kb * 64;
        __syncthreads();

#pragma unroll
        for (int it = 0; it < 4; it++) {
            int e   = tid + it * 256;
            int row = e >> 4;
            int c4  = (e & 15) << 2;
            float4 kv = *(const float4*)&K[(size_t)(ks + row) * DMODEL + hoff + c4];
            KPs[c4 + 0][row] = kv.x;
            KPs[c4 + 1][row] = kv.y;
            KPs[c4 + 2][row] = kv.z;
            KPs[c4 + 3][row] = kv.w;
            float4 vv = *(const float4*)&V[(size_t)(ks + row) * DMODEL + hoff + c4];
            *(float4*)&Vs[row][c4] = vv;
        }
        __syncthreads();

        float s[4][4];
#pragma unroll
        for (int r = 0; r < 4; r++)
#pragma unroll
            for (int c = 0; c < 4; c++) s[r][c] = 0.0f;
#pragma unroll
        for (int c = 0; c < DH; c++) {
            float4 q4 = *(const float4*)&Qs[c][ty * 4];
            float4 k4 = *(const float4*)&KPs[c][tx * 4];
            float rq[4] = {q4.x, q4.y, q4.z, q4.w};
            float rk[4] = {k4.x, k4.y, k4.z, k4.w};
#pragma unroll
            for (int r = 0; r < 4; r++)
#pragma unroll
                for (int cc = 0; cc < 4; cc++)
                    s[r][cc] += rq[r] * rk[cc];
        }

        if (kb == nkb) {
#pragma unroll
            for (int r = 0; r < 4; r++)
#pragma unroll
                for (int cc = 0; cc < 4; cc++)
                    if (ks + tx * 4 + cc > qs + ty * 4 + r)
                        s[r][cc] = -3.0e38f;
        }

#pragma unroll
        for (int r = 0; r < 4; r++) {
            float mx = fmaxf(fmaxf(s[r][0], s[r][1]), fmaxf(s[r][2], s[r][3]));
#pragma unroll
            for (int off = 8; off > 0; off >>= 1)
                mx = fmaxf(mx, __shfl_xor_sync(0xffffffffu, mx, off));
            float mnew  = fmaxf(m[r], mx);
            float alpha = __expf(m[r] - mnew);
            m[r] = mnew;
            float rs = 0.0f;
#pragma unroll
            for (int cc = 0; cc < 4; cc++) {
                s[r][cc] = __expf(s[r][cc] - mnew);
                rs += s[r][cc];
            }
#pragma unroll
            for (int off = 8; off > 0; off >>= 1)
                rs += __shfl_xor_sync(0xffffffffu, rs, off);
            l[r] = l[r] * alpha + rs;
#pragma unroll
            for (int cc = 0; cc < 4; cc++) o[r][cc] *= alpha;
        }

        __syncthreads();
#pragma unroll
        for (int r = 0; r < 4; r++)
#pragma unroll
            for (int cc = 0; cc < 4; cc++)
                KPs[ty * 4 + r][tx * 4 + cc] = s[r][cc];
        __syncthreads();

#pragma unroll 8
        for (int j = 0; j < 64; j++) {
            float4 v4 = *(const float4*)&Vs[j][tx * 4];
#pragma unroll
            for (int r = 0; r < 4; r++) {
                float p = KPs[ty * 4 + r][j];
                o[r][0] += p * v4.x;
                o[r][1] += p * v4.y;
                o[r][2] += p * v4.z;
                o[r][3] += p * v4.w;
            }
        }
    }

#pragma unroll
    for (int r = 0; r < 4; r++) {
        float inv = 1.0f / l[r];
        *(float4*)&O[(size_t)(qs + ty * 4 + r) * DMODEL + hoff + tx * 4] =
            make_float4(o[r][0] * inv, o[r][1] * inv, o[r][2] * inv, o[r][3] * inv);
    }
}

// ============================================================================
extern "C" void kernel_launch(void* const* d_in, const int* in_sizes, int n_in,
                              void* d_out, int out_size)
{
    const float* x  = (const float*)d_in[0];
    const float* Wq = (const float*)d_in[1];
    const float* Wk = (const float*)d_in[2];
    const float* Wv = (const float*)d_in[3];
    const float* Wo = (const float*)d_in[4];
    float* out = (float*)d_out;

    float *Qp, *Kp, *Vp, *Op;
    __nv_bfloat16 *xhi, *xlo, *ohi, *olo, *wthi, *wtlo;
    cudaGetSymbolAddress((void**)&Qp,  g_Q);
    cudaGetSymbolAddress((void**)&Kp,  g_K);
    cudaGetSymbolAddress((void**)&Vp,  g_V);
    cudaGetSymbolAddress((void**)&Op,  g_O);
    cudaGetSymbolAddress((void**)&xhi, g_xhi);
    cudaGetSymbolAddress((void**)&xlo, g_xlo);
    cudaGetSymbolAddress((void**)&ohi, g_Ohi);
    cudaGetSymbolAddress((void**)&olo, g_Olo);
    cudaGetSymbolAddress((void**)&wthi, g_Wthi);
    cudaGetSymbolAddress((void**)&wtlo, g_Wtlo);

    cudaFuncSetAttribute(gemm_tc, cudaFuncAttributeMaxDynamicSharedMemorySize,
                         GEMM_SMEM);

    const size_t WSZ = (size_t)DMODEL * DMODEL;
    const int n4 = N_TOK * DMODEL / 4;

    // split x into bf16 hi/lo
    split_rows<<<(n4 + 255) / 256, 256>>>(x, xhi, xlo, n4);

    // transpose+split all four weights
    dim3 tb(32, 8), tg(DMODEL / 32, DMODEL / 32);
    split_transpose<<<tg, tb>>>(Wq, wthi + 0 * WSZ, wtlo + 0 * WSZ);
    split_transpose<<<tg, tb>>>(Wk, wthi + 1 * WSZ, wtlo + 1 * WSZ);
    split_transpose<<<tg, tb>>>(Wv, wthi + 2 * WSZ, wtlo + 2 * WSZ);
    split_transpose<<<tg, tb>>>(Wo, wthi + 3 * WSZ, wtlo + 3 * WSZ);

    // Q/K/V projections on tensor cores
    dim3 gg(DMODEL / 128, N_TOK / 128);   // (8, 32)
    gemm_tc<<<gg, 256, GEMM_SMEM>>>(xhi, xlo, wthi + 0 * WSZ, wtlo + 0 * WSZ, Qp);
    gemm_tc<<<gg, 256, GEMM_SMEM>>>(xhi, xlo, wthi + 1 * WSZ, wtlo + 1 * WSZ, Kp);
    gemm_tc<<<gg, 256, GEMM_SMEM>>>(xhi, xlo, wthi + 2 * WSZ, wtlo + 2 * WSZ, Vp);

    int norm_blocks = (N_TOK * HEADS) / 8;
    l2norm_kernel<<<norm_blocks, 256>>>(Qp, 8.0f);   // SCALE folded into Q
    l2norm_kernel<<<norm_blocks, 256>>>(Kp, 1.0f);

    dim3 fa_grid(N_TOK / 64, HEADS);
    dim3 blk(16, 16);
    flash_attn<<<fa_grid, blk>>>(Qp, Kp, Vp, Op);

    // output projection on tensor cores
    split_rows<<<(n4 + 255) / 256, 256>>>(Op, ohi, olo, n4);
    gemm_tc<<<gg, 256, GEMM_SMEM>>>(ohi, olo, wthi + 3 * WSZ, wtlo + 3 * WSZ, out);
}

// round 12
// speedup vs baseline: 1.6466x; 1.3033x over previous
#include <cuda_runtime.h>
#include <cuda_bf16.h>
#include <math.h>
#include <stdint.h>

#define N_TOK  4096
#define DMODEL 1024
#define HEADS  16
#define DH     64

// ---- scratch (no allocations allowed) ----
__device__ float g_Q[N_TOK * DMODEL];
__device__ float g_K[N_TOK * DMODEL];
__device__ float g_V[N_TOK * DMODEL];
__device__ float g_O[N_TOK * DMODEL];
__device__ __nv_bfloat16 g_xhi[N_TOK * DMODEL];
__device__ __nv_bfloat16 g_xlo[N_TOK * DMODEL];
__device__ __nv_bfloat16 g_Qhi[N_TOK * DMODEL];
__device__ __nv_bfloat16 g_Qlo[N_TOK * DMODEL];
__device__ __nv_bfloat16 g_Khi[N_TOK * DMODEL];
__device__ __nv_bfloat16 g_Klo[N_TOK * DMODEL];
__device__ __nv_bfloat16 g_Vhi[N_TOK * DMODEL];
__device__ __nv_bfloat16 g_Vlo[N_TOK * DMODEL];
__device__ __nv_bfloat16 g_Ohi[N_TOK * DMODEL];
__device__ __nv_bfloat16 g_Olo[N_TOK * DMODEL];
__device__ __nv_bfloat16 g_Wthi[4][DMODEL * DMODEL];   // W^T, bf16 hi
__device__ __nv_bfloat16 g_Wtlo[4][DMODEL * DMODEL];   // W^T, bf16 lo

// ============================================================================
// Base-ISA helpers (NO tcgen05 — ptxas here targets plain sm_103)
// ============================================================================
static __device__ __forceinline__ uint32_t smem_u32(const void* p) {
    uint32_t a;
    asm("{ .reg .u64 t; cvta.to.shared.u64 t, %1; cvt.u32.u64 %0, t; }"
        : "=r"(a) : "l"(p));
    return a;
}
static __device__ __forceinline__ void cp_async16(uint32_t saddr, const void* gaddr) {
    asm volatile("cp.async.cg.shared.global [%0], [%1], 16;"
                 :: "r"(saddr), "l"(gaddr) : "memory");
}
#define CP_COMMIT() asm volatile("cp.async.commit_group;" ::: "memory")
#define CP_WAIT(n)  asm volatile("cp.async.wait_group %0;" :: "n"(n) : "memory")

static __device__ __forceinline__ void ldsm_x4(uint32_t* r, uint32_t addr) {
    asm volatile("ldmatrix.sync.aligned.m8n8.x4.shared.b16 {%0,%1,%2,%3}, [%4];"
                 : "=r"(r[0]), "=r"(r[1]), "=r"(r[2]), "=r"(r[3]) : "r"(addr));
}
static __device__ __forceinline__ void ldsm_x4_t(uint32_t* r, uint32_t addr) {
    asm volatile("ldmatrix.sync.aligned.m8n8.x4.trans.shared.b16 {%0,%1,%2,%3}, [%4];"
                 : "=r"(r[0]), "=r"(r[1]), "=r"(r[2]), "=r"(r[3]) : "r"(addr));
}
static __device__ __forceinline__ void mma_bf16(float* d, const uint32_t* a,
                                                uint32_t b0, uint32_t b1) {
    asm volatile(
        "mma.sync.aligned.m16n8k16.row.col.f32.bf16.bf16.f32 "
        "{%0,%1,%2,%3}, {%4,%5,%6,%7}, {%8,%9}, {%0,%1,%2,%3};"
        : "+f"(d[0]), "+f"(d[1]), "+f"(d[2]), "+f"(d[3])
        : "r"(a[0]), "r"(a[1]), "r"(a[2]), "r"(a[3]), "r"(b0), "r"(b1));
}
// pack two fp32 (lo,hi) into bf16x2 register
static __device__ __forceinline__ uint32_t pack_bf16x2(float lo, float hi) {
    uint32_t d;
    asm("cvt.rn.bf16x2.f32 %0, %1, %2;" : "=r"(d) : "f"(hi), "f"(lo));
    return d;
}

// ============================================================================
// Pre-pass: split fp32 -> bf16 hi/lo (row-preserving)
// ============================================================================
__global__ __launch_bounds__(256) void split_rows(
    const float* __restrict__ in, __nv_bfloat16* __restrict__ hi,
    __nv_bfloat16* __restrict__ lo, int n4)
{
    int i = blockIdx.x * 256 + threadIdx.x;
    if (i >= n4) return;
    float4 v = ((const float4*)in)[i];
    float a[4] = {v.x, v.y, v.z, v.w};
    __nv_bfloat16 h[4], l[4];
#pragma unroll
    for (int j = 0; j < 4; j++) {
        h[j] = __float2bfloat16(a[j]);
        l[j] = __float2bfloat16(a[j] - __bfloat162float(h[j]));
    }
    __nv_bfloat162* hp = (__nv_bfloat162*)(hi + (size_t)i * 4);
    __nv_bfloat162* lp = (__nv_bfloat162*)(lo + (size_t)i * 4);
    hp[0] = __nv_bfloat162(h[0], h[1]);
    hp[1] = __nv_bfloat162(h[2], h[3]);
    lp[0] = __nv_bfloat162(l[0], l[1]);
    lp[1] = __nv_bfloat162(l[2], l[3]);
}

// ============================================================================
// Pre-pass: W [K,N] fp32 -> W^T [N,K] bf16 hi/lo (tiled transpose)
// ============================================================================
__global__ __launch_bounds__(256) void split_transpose(
    const float* __restrict__ W, __nv_bfloat16* __restrict__ Thi,
    __nv_bfloat16* __restrict__ Tlo)
{
    __shared__ float ts[32][33];
    int tx = threadIdx.x, ty = threadIdx.y;   // 32 x 8
    int x = blockIdx.x * 32 + tx;
#pragma unroll
    for (int i = 0; i < 4; i++)
        ts[ty + i * 8][tx] = W[(size_t)(blockIdx.y * 32 + ty + i * 8) * DMODEL + x];
    __syncthreads();
    int ox = blockIdx.y * 32 + tx;
#pragma unroll
    for (int i = 0; i < 4; i++) {
        float a = ts[tx][ty + i * 8];
        __nv_bfloat16 h = __float2bfloat16(a);
        size_t idx = (size_t)(blockIdx.x * 32 + ty + i * 8) * DMODEL + ox;
        Thi[idx] = h;
        Tlo[idx] = __float2bfloat16(a - __bfloat162float(h));
    }
}

// ============================================================================
// Fused L2-normalize (+scale) and bf16 hi/lo split. One warp per (token,head).
// ============================================================================
__global__ __launch_bounds__(256) void l2norm_split(
    const float* __restrict__ X, __nv_bfloat16* __restrict__ hi,
    __nv_bfloat16* __restrict__ lo, float scale)
{
    int warp = (blockIdx.x * blockDim.x + threadIdx.x) >> 5;
    int lane = threadIdx.x & 31;
    if (warp >= N_TOK * HEADS) return;
    size_t base = (size_t)(warp / HEADS) * DMODEL + (warp % HEADS) * DH;
    const float* p = X + base;
    float a = p[lane];
    float b = p[lane + 32];
    float ss = a * a + b * b;
#pragma unroll
    for (int off = 16; off > 0; off >>= 1)
        ss += __shfl_xor_sync(0xffffffffu, ss, off);
    float inv = scale / fmaxf(sqrtf(ss), 1e-12f);
    a *= inv; b *= inv;
    __nv_bfloat16 ah = __float2bfloat16(a), bh = __float2bfloat16(b);
    hi[base + lane]      = ah;
    hi[base + lane + 32] = bh;
    lo[base + lane]      = __float2bfloat16(a - __bfloat162float(ah));
    lo[base + lane + 32] = __float2bfloat16(b - __bfloat162float(bh));
}

// ============================================================================
// Tensor-core GEMM via mma.sync (base ISA): C[M,N] = A @ B^T
// ============================================================================
#define KC 32
#define KP 40
#define TB (128 * KP * 2)              // bytes per tensor tile: 10240
#define OFF_AH 0
#define OFF_AL (TB)
#define OFF_BH (2 * TB)
#define OFF_BL (3 * TB)
#define STAGE_B (4 * TB)               // 40960
#define GEMM_SMEM (2 * STAGE_B)        // 81920

__global__ __launch_bounds__(256) void gemm_tc(
    const __nv_bfloat16* __restrict__ Ahi, const __nv_bfloat16* __restrict__ Alo,
    const __nv_bfloat16* __restrict__ Bhi, const __nv_bfloat16* __restrict__ Blo,
    float* __restrict__ C)
{
    extern __shared__ char smem[];
    const uint32_t sbase = smem_u32(smem);
    const int tid  = threadIdx.x;
    const int lane = tid & 31, warp = tid >> 5;
    const int wm = warp >> 2, wn = warp & 3;          // 2 x 4 warp grid
    const int m0 = blockIdx.y * 128, n0 = blockIdx.x * 128;

    const int lrow0 = tid >> 1;
    const int lsg0  = (tid & 1) * 2;

    float acc[4][4][4];
#pragma unroll
    for (int i = 0; i < 4; i++)
#pragma unroll
        for (int j = 0; j < 4; j++)
#pragma unroll
            for (int r = 0; r < 4; r++) acc[i][j][r] = 0.0f;

    const int NSTG = DMODEL / KC;

#pragma unroll
    for (int q = 0; q < 2; q++) {
        int sg = lsg0 + q;
        uint32_t so = (uint32_t)(lrow0 * KP * 2 + sg * 16);
        size_t ga = (size_t)(m0 + lrow0) * DMODEL + sg * 8;
        size_t gb = (size_t)(n0 + lrow0) * DMODEL + sg * 8;
        cp_async16(sbase + OFF_AH + so, Ahi + ga);
        cp_async16(sbase + OFF_AL + so, Alo + ga);
        cp_async16(sbase + OFF_BH + so, Bhi + gb);
        cp_async16(sbase + OFF_BL + so, Blo + gb);
    }
    CP_COMMIT();

    const uint32_t a_r = (uint32_t)((lane & 15));
    const uint32_t a_c = (uint32_t)(((lane >> 4) << 3));
    const uint32_t b_r = (uint32_t)((lane & 7) + ((lane >> 4) << 3));
    const uint32_t b_c = (uint32_t)((((lane >> 3) & 1) << 3));

    for (int s = 0; s < NSTG; s++) {
        if (s + 1 < NSTG) {
            const int k0 = (s + 1) * KC;
            const uint32_t bb = sbase + ((s + 1) & 1) * STAGE_B;
#pragma unroll
            for (int q = 0; q < 2; q++) {
                int sg = lsg0 + q;
                uint32_t so = (uint32_t)(lrow0 * KP * 2 + sg * 16);
                size_t ga = (size_t)(m0 + lrow0) * DMODEL + k0 + sg * 8;
                size_t gb = (size_t)(n0 + lrow0) * DMODEL + k0 + sg * 8;
                cp_async16(bb + OFF_AH + so, Ahi + ga);
                cp_async16(bb + OFF_AL + so, Alo + ga);
                cp_async16(bb + OFF_BH + so, Bhi + gb);
                cp_async16(bb + OFF_BL + so, Blo + gb);
            }
            CP_COMMIT();
            CP_WAIT(1);
        } else {
            CP_WAIT(0);
        }
        __syncthreads();

        const uint32_t bb = sbase + (s & 1) * STAGE_B;
#pragma unroll
        for (int ks = 0; ks < 2; ks++) {
            uint32_t ah[4][4], al[4][4], bh[2][4], bl[2][4];
            const uint32_t acol = (uint32_t)(ks * 16) + a_c;
            const uint32_t bcol = (uint32_t)(ks * 16) + b_c;
#pragma unroll
            for (int i = 0; i < 4; i++) {
                uint32_t off = ((uint32_t)(wm * 64 + i * 16) + a_r) * (KP * 2) + acol * 2;
                ldsm_x4(ah[i], bb + OFF_AH + off);
                ldsm_x4(al[i], bb + OFF_AL + off);
            }
#pragma unroll
            for (int j2 = 0; j2 < 2; j2++) {
                uint32_t off = ((uint32_t)(wn * 32 + j2 * 16) + b_r) * (KP * 2) + bcol * 2;
                ldsm_x4(bh[j2], bb + OFF_BH + off);
                ldsm_x4(bl[j2], bb + OFF_BL + off);
            }
#pragma unroll
            for (int i = 0; i < 4; i++)
#pragma unroll
                for (int j = 0; j < 4; j++) {
                    int j2 = j >> 1, jr = (j & 1) * 2;
                    mma_bf16(acc[i][j], ah[i], bh[j2][jr], bh[j2][jr + 1]);
                    mma_bf16(acc[i][j], ah[i], bl[j2][jr], bl[j2][jr + 1]);
                    mma_bf16(acc[i][j], al[i], bh[j2][jr], bh[j2][jr + 1]);
                }
        }
        __syncthreads();
    }

    const int gq = lane >> 2, tq = lane & 3;
#pragma unroll
    for (int i = 0; i < 4; i++) {
        int row = m0 + wm * 64 + i * 16 + gq;
#pragma unroll
        for (int j = 0; j < 4; j++) {
            int col = n0 + wn * 32 + j * 8 + tq * 2;
            *(float2*)&C[(size_t)row * DMODEL + col] =
                make_float2(acc[i][j][0], acc[i][j][1]);
            *(float2*)&C[(size_t)(row + 8) * DMODEL + col] =
                make_float2(acc[i][j][2], acc[i][j][3]);
        }
    }
}

// ============================================================================
// Tensor-core flash attention (causal), 3-term bf16 split everywhere.
// CTA: 64 queries x one head, 4 warps (16 query rows each), 128 threads.
// K/V 64-key tiles double-buffered via cp.async. Row pitch 72 bf16 (144B).
// ============================================================================
#define FKP 72
#define FTB (64 * FKP * 2)            // 9216 bytes per tile
#define F_QH 0
#define F_QL FTB
#define F_ST (2 * FTB)                // stage region start
#define F_SS (4 * FTB)                // stage stride (kh,kl,vh,vl)
#define F_KH 0
#define F_KL FTB
#define F_VH (2 * FTB)
#define F_VL (3 * FTB)
#define FLASH_SMEM (2 * FTB + 2 * F_SS)   // 92160

__global__ __launch_bounds__(128) void flash_tc(
    const __nv_bfloat16* __restrict__ Qhi, const __nv_bfloat16* __restrict__ Qlo,
    const __nv_bfloat16* __restrict__ Khi, const __nv_bfloat16* __restrict__ Klo,
    const __nv_bfloat16* __restrict__ Vhi, const __nv_bfloat16* __restrict__ Vlo,
    float* __restrict__ O)
{
    extern __shared__ char smem[];
    const uint32_t sbase = smem_u32(smem);
    const int tid = threadIdx.x;
    const int lane = tid & 31, w = tid >> 5;
    const int qi = gridDim.x - 1 - blockIdx.x;      // heavy blocks first
    const int qs = qi * 64;
    const int hoff = blockIdx.y * DH;

    // loader coords: row = tid>>1 (0..63), 4 segs of 16B each half-row
    const int lrow = tid >> 1;
    const int lsg0 = (tid & 1) * 4;

    // ---- issue Q + stage0 loads ----
#pragma unroll
    for (int q = 0; q < 4; q++) {
        int sg = lsg0 + q;
        uint32_t so = (uint32_t)(lrow * FKP * 2 + sg * 16);
        size_t gq = (size_t)(qs + lrow) * DMODEL + hoff + sg * 8;
        cp_async16(sbase + F_QH + so, Qhi + gq);
        cp_async16(sbase + F_QL + so, Qlo + gq);
        size_t gk = (size_t)lrow * DMODEL + hoff + sg * 8;   // key tile 0
        cp_async16(sbase + F_ST + F_KH + so, Khi + gk);
        cp_async16(sbase + F_ST + F_KL + so, Klo + gk);
        cp_async16(sbase + F_ST + F_VH + so, Vhi + gk);
        cp_async16(sbase + F_ST + F_VL + so, Vlo + gk);
    }
    CP_COMMIT();

    // fragment lane mappings
    const uint32_t a_r = (uint32_t)(lane & 15);
    const uint32_t a_c = (uint32_t)((lane >> 4) << 3);
    const uint32_t b_r = (uint32_t)((lane & 7) + ((lane >> 4) << 3));
    const uint32_t b_c = (uint32_t)(((lane >> 3) & 1) << 3);
    const uint32_t v_r = (uint32_t)((lane & 7) + (((lane >> 3) & 1) << 3));
    const uint32_t v_c = (uint32_t)((lane >> 4) << 3);

    uint32_t qfh[4][4], qfl[4][4];
    float o[8][4];
#pragma unroll
    for (int t = 0; t < 8; t++)
#pragma unroll
        for (int r = 0; r < 4; r++) o[t][r] = 0.0f;
    float m0 = -3.0e38f, m1 = -3.0e38f, l0 = 0.0f, l1 = 0.0f;

    for (int kb = 0; kb <= qi; kb++) {
        if (kb < qi) {
            const uint32_t bb = sbase + F_ST + ((kb + 1) & 1) * F_SS;
            const size_t kt = (size_t)((kb + 1) * 64);
#pragma unroll
            for (int q = 0; q < 4; q++) {
                int sg = lsg0 + q;
                uint32_t so = (uint32_t)(lrow * FKP * 2 + sg * 16);
                size_t gk = (kt + lrow) * DMODEL + hoff + sg * 8;
                cp_async16(bb + F_KH + so, Khi + gk);
                cp_async16(bb + F_KL + so, Klo + gk);
                cp_async16(bb + F_VH + so, Vhi + gk);
                cp_async16(bb + F_VL + so, Vlo + gk);
            }
            CP_COMMIT();
            CP_WAIT(1);
        } else {
            CP_WAIT(0);
        }
        __syncthreads();

        if (kb == 0) {   // Q fragments (once)
#pragma unroll
            for (int ks = 0; ks < 4; ks++) {
                uint32_t off = ((uint32_t)(w * 16) + a_r) * (FKP * 2)
                             + ((uint32_t)(ks * 16) + a_c) * 2;
                ldsm_x4(qfh[ks], sbase + F_QH + off);
                ldsm_x4(qfl[ks], sbase + F_QL + off);
            }
        }

        const uint32_t bb = sbase + F_ST + (kb & 1) * F_SS;

        // ---- S = Q K^T (3-term) ----
        float sacc[8][4];
#pragma unroll
        for (int t = 0; t < 8; t++)
#pragma unroll
            for (int r = 0; r < 4; r++) sacc[t][r] = 0.0f;
#pragma unroll
        for (int ks = 0; ks < 4; ks++) {
#pragma unroll
            for (int p = 0; p < 4; p++) {
                uint32_t kh4[4], kl4[4];
                uint32_t off = ((uint32_t)(p * 16) + b_r) * (FKP * 2)
                             + ((uint32_t)(ks * 16) + b_c) * 2;
                ldsm_x4(kh4, bb + F_KH + off);
                ldsm_x4(kl4, bb + F_KL + off);
                mma_bf16(sacc[2 * p],     qfh[ks], kh4[0], kh4[1]);
                mma_bf16(sacc[2 * p + 1], qfh[ks], kh4[2], kh4[3]);
                mma_bf16(sacc[2 * p],     qfh[ks], kl4[0], kl4[1]);
                mma_bf16(sacc[2 * p + 1], qfh[ks], kl4[2], kl4[3]);
                mma_bf16(sacc[2 * p],     qfl[ks], kh4[0], kh4[1]);
                mma_bf16(sacc[2 * p + 1], qfl[ks], kh4[2], kh4[3]);
            }
        }

        // ---- causal mask on diagonal tile ----
        const int q0 = w * 16 + (lane >> 2), q1 = q0 + 8;
        if (kb == qi) {
#pragma unroll
            for (int t = 0; t < 8; t++) {
                int k0 = t * 8 + 2 * (lane & 3);
                if (k0     > q0) sacc[t][0] = -3.0e38f;
                if (k0 + 1 > q0) sacc[t][1] = -3.0e38f;
                if (k0     > q1) sacc[t][2] = -3.0e38f;
                if (k0 + 1 > q1) sacc[t][3] = -3.0e38f;
            }
        }

        // ---- online softmax (two rows per lane) ----
        float mx0 = -3.0e38f, mx1 = -3.0e38f;
#pragma unroll
        for (int t = 0; t < 8; t++) {
            mx0 = fmaxf(mx0, fmaxf(sacc[t][0], sacc[t][1]));
            mx1 = fmaxf(mx1, fmaxf(sacc[t][2], sacc[t][3]));
        }
        mx0 = fmaxf(mx0, __shfl_xor_sync(0xffffffffu, mx0, 1));
        mx0 = fmaxf(mx0, __shfl_xor_sync(0xffffffffu, mx0, 2));
        mx1 = fmaxf(mx1, __shfl_xor_sync(0xffffffffu, mx1, 1));
        mx1 = fmaxf(mx1, __shfl_xor_sync(0xffffffffu, mx1, 2));
        float mn0 = fmaxf(m0, mx0), mn1 = fmaxf(m1, mx1);
        float al0 = __expf(m0 - mn0), al1 = __expf(m1 - mn1);
        m0 = mn0; m1 = mn1;
        float rs0 = 0.0f, rs1 = 0.0f;
#pragma unroll
        for (int t = 0; t < 8; t++) {
            sacc[t][0] = __expf(sacc[t][0] - mn0);
            sacc[t][1] = __expf(sacc[t][1] - mn0);
            sacc[t][2] = __expf(sacc[t][2] - mn1);
            sacc[t][3] = __expf(sacc[t][3] - mn1);
            rs0 += sacc[t][0] + sacc[t][1];
            rs1 += sacc[t][2] + sacc[t][3];
        }
        rs0 += __shfl_xor_sync(0xffffffffu, rs0, 1);
        rs0 += __shfl_xor_sync(0xffffffffu, rs0, 2);
        rs1 += __shfl_xor_sync(0xffffffffu, rs1, 1);
        rs1 += __shfl_xor_sync(0xffffffffu, rs1, 2);
        l0 = l0 * al0 + rs0;
        l1 = l1 * al1 + rs1;
#pragma unroll
        for (int t = 0; t < 8; t++) {
            o[t][0] *= al0; o[t][1] *= al0;
            o[t][2] *= al1; o[t][3] *= al1;
        }

        // ---- O += P V (3-term, P split in-register) ----
#pragma unroll
        for (int kc = 0; kc < 4; kc++) {
            float pv[8] = { sacc[2 * kc][0],     sacc[2 * kc][1],
                            sacc[2 * kc][2],     sacc[2 * kc][3],
                            sacc[2 * kc + 1][0], sacc[2 * kc + 1][1],
                            sacc[2 * kc + 1][2], sacc[2 * kc + 1][3] };
            uint32_t aph[4], apl[4];
#pragma unroll
            for (int h = 0; h < 4; h++) {
                float e0 = pv[2 * h], e1 = pv[2 * h + 1];
                float h0 = __bfloat162float(__float2bfloat16(e0));
                float h1 = __bfloat162float(__float2bfloat16(e1));
                aph[h] = pack_bf16x2(h0, h1);
                apl[h] = pack_bf16x2(e0 - h0, e1 - h1);
            }
#pragma unroll
            for (int dp = 0; dp < 4; dp++) {
                uint32_t vh4[4], vl4[4];
                uint32_t off = ((uint32_t)(kc * 16) + v_r) * (FKP * 2)
                             + ((uint32_t)(dp * 16) + v_c) * 2;
                ldsm_x4_t(vh4, bb + F_VH + off);
                ldsm_x4_t(vl4, bb + F_VL + off);
                mma_bf16(o[2 * dp],     aph, vh4[0], vh4[1]);
                mma_bf16(o[2 * dp + 1], aph, vh4[2], vh4[3]);
                mma_bf16(o[2 * dp],     aph, vl4[0], vl4[1]);
                mma_bf16(o[2 * dp + 1], aph, vl4[2], vl4[3]);
                mma_bf16(o[2 * dp],     apl, vh4[0], vh4[1]);
                mma_bf16(o[2 * dp + 1], apl, vh4[2], vh4[3]);
            }
        }
        __syncthreads();
    }

    // ---- epilogue ----
    float inv0 = 1.0f / l0, inv1 = 1.0f / l1;
    int r0 = qs + w * 16 + (lane >> 2);
#pragma unroll
    for (int t = 0; t < 8; t++) {
        int col = hoff + t * 8 + 2 * (lane & 3);
        *(float2*)&O[(size_t)r0 * DMODEL + col] =
            make_float2(o[t][0] * inv0, o[t][1] * inv0);
        *(float2*)&O[(size_t)(r0 + 8) * DMODEL + col] =
            make_float2(o[t][2] * inv1, o[t][3] * inv1);
    }
}

// ============================================================================
extern "C" void kernel_launch(void* const* d_in, const int* in_sizes, int n_in,
                              void* d_out, int out_size)
{
    const float* x  = (const float*)d_in[0];
    const float* Wq = (const float*)d_in[1];
    const float* Wk = (const float*)d_in[2];
    const float* Wv = (const float*)d_in[3];
    const float* Wo = (const float*)d_in[4];
    float* out = (float*)d_out;

    float *Qp, *Kp, *Vp, *Op;
    __nv_bfloat16 *xhi, *xlo, *qhi, *qlo, *khi, *klo, *vhi, *vlo, *ohi, *olo,
                  *wthi, *wtlo;
    cudaGetSymbolAddress((void**)&Qp,  g_Q);
    cudaGetSymbolAddress((void**)&Kp,  g_K);
    cudaGetSymbolAddress((void**)&Vp,  g_V);
    cudaGetSymbolAddress((void**)&Op,  g_O);
    cudaGetSymbolAddress((void**)&xhi, g_xhi);
    cudaGetSymbolAddress((void**)&xlo, g_xlo);
    cudaGetSymbolAddress((void**)&qhi, g_Qhi);
    cudaGetSymbolAddress((void**)&qlo, g_Qlo);
    cudaGetSymbolAddress((void**)&khi, g_Khi);
    cudaGetSymbolAddress((void**)&klo, g_Klo);
    cudaGetSymbolAddress((void**)&vhi, g_Vhi);
    cudaGetSymbolAddress((void**)&vlo, g_Vlo);
    cudaGetSymbolAddress((void**)&ohi, g_Ohi);
    cudaGetSymbolAddress((void**)&olo, g_Olo);
    cudaGetSymbolAddress((void**)&wthi, g_Wthi);
    cudaGetSymbolAddress((void**)&wtlo, g_Wtlo);

    cudaFuncSetAttribute(gemm_tc, cudaFuncAttributeMaxDynamicSharedMemorySize,
                         GEMM_SMEM);
    cudaFuncSetAttribute(flash_tc, cudaFuncAttributeMaxDynamicSharedMemorySize,
                         FLASH_SMEM);

    const size_t WSZ = (size_t)DMODEL * DMODEL;
    const int n4 = N_TOK * DMODEL / 4;

    split_rows<<<(n4 + 255) / 256, 256>>>(x, xhi, xlo, n4);

    dim3 tb(32, 8), tg(DMODEL / 32, DMODEL / 32);
    split_transpose<<<tg, tb>>>(Wq, wthi + 0 * WSZ, wtlo + 0 * WSZ);
    split_transpose<<<tg, tb>>>(Wk, wthi + 1 * WSZ, wtlo + 1 * WSZ);
    split_transpose<<<tg, tb>>>(Wv, wthi + 2 * WSZ, wtlo + 2 * WSZ);
    split_transpose<<<tg, tb>>>(Wo, wthi + 3 * WSZ, wtlo + 3 * WSZ);

    dim3 gg(DMODEL / 128, N_TOK / 128);   // (8, 32)
    gemm_tc<<<gg, 256, GEMM_SMEM>>>(xhi, xlo, wthi + 0 * WSZ, wtlo + 0 * WSZ, Qp);
    gemm_tc<<<gg, 256, GEMM_SMEM>>>(xhi, xlo, wthi + 1 * WSZ, wtlo + 1 * WSZ, Kp);
    gemm_tc<<<gg, 256, GEMM_SMEM>>>(xhi, xlo, wthi + 2 * WSZ, wtlo + 2 * WSZ, Vp);

    int norm_blocks = (N_TOK * HEADS) / 8;
    l2norm_split<<<norm_blocks, 256>>>(Qp, qhi, qlo, 8.0f);  // SCALE folded into Q
    l2norm_split<<<norm_blocks, 256>>>(Kp, khi, klo, 1.0f);
    split_rows<<<(n4 + 255) / 256, 256>>>(Vp, vhi, vlo, n4);

    dim3 fa_grid(N_TOK / 64, HEADS);
    flash_tc<<<fa_grid, 128, FLASH_SMEM>>>(qhi, qlo, khi, klo, vhi, vlo, Op);

    split_rows<<<(n4 + 255) / 256, 256>>>(Op, ohi, olo, n4);
    gemm_tc<<<gg, 256, GEMM_SMEM>>>(ohi, olo, wthi + 3 * WSZ, wtlo + 3 * WSZ, out);
}

// round 14
// speedup vs baseline: 2.6112x; 1.5858x over previous
#include <cuda_runtime.h>
#include <cuda_bf16.h>
#include <math.h>
#include <stdint.h>

#define N_TOK  4096
#define DMODEL 1024
#define HEADS  16
#define DH     64

// ---- scratch (no allocations allowed) ----
__device__ float g_Q[N_TOK * DMODEL];
__device__ float g_K[N_TOK * DMODEL];
__device__ float g_V[N_TOK * DMODEL];
__device__ __nv_bfloat16 g_xhi[N_TOK * DMODEL];
__device__ __nv_bfloat16 g_xlo[N_TOK * DMODEL];
__device__ __nv_bfloat16 g_Qhi[N_TOK * DMODEL];
__device__ __nv_bfloat16 g_Qlo[N_TOK * DMODEL];
__device__ __nv_bfloat16 g_Khi[N_TOK * DMODEL];
__device__ __nv_bfloat16 g_Klo[N_TOK * DMODEL];
__device__ __nv_bfloat16 g_Vhi[N_TOK * DMODEL];
__device__ __nv_bfloat16 g_Vlo[N_TOK * DMODEL];
__device__ __nv_bfloat16 g_Ohi[N_TOK * DMODEL];
__device__ __nv_bfloat16 g_Olo[N_TOK * DMODEL];
__device__ __nv_bfloat16 g_Wthi[4][DMODEL * DMODEL];   // W^T, bf16 hi
__device__ __nv_bfloat16 g_Wtlo[4][DMODEL * DMODEL];   // W^T, bf16 lo

// ============================================================================
// Base-ISA helpers (NO tcgen05 — ptxas here targets plain sm_103)
// ============================================================================
static __device__ __forceinline__ uint32_t smem_u32(const void* p) {
    uint32_t a;
    asm("{ .reg .u64 t; cvta.to.shared.u64 t, %1; cvt.u32.u64 %0, t; }"
        : "=r"(a) : "l"(p));
    return a;
}
static __device__ __forceinline__ void cp_async16(uint32_t saddr, const void* gaddr) {
    asm volatile("cp.async.cg.shared.global [%0], [%1], 16;"
                 :: "r"(saddr), "l"(gaddr) : "memory");
}
#define CP_COMMIT() asm volatile("cp.async.commit_group;" ::: "memory")
#define CP_WAIT(n)  asm volatile("cp.async.wait_group %0;" :: "n"(n) : "memory")

static __device__ __forceinline__ void ldsm_x4(uint32_t* r, uint32_t addr) {
    asm volatile("ldmatrix.sync.aligned.m8n8.x4.shared.b16 {%0,%1,%2,%3}, [%4];"
                 : "=r"(r[0]), "=r"(r[1]), "=r"(r[2]), "=r"(r[3]) : "r"(addr));
}
static __device__ __forceinline__ void ldsm_x4_t(uint32_t* r, uint32_t addr) {
    asm volatile("ldmatrix.sync.aligned.m8n8.x4.trans.shared.b16 {%0,%1,%2,%3}, [%4];"
                 : "=r"(r[0]), "=r"(r[1]), "=r"(r[2]), "=r"(r[3]) : "r"(addr));
}
static __device__ __forceinline__ void mma_bf16(float* d, const uint32_t* a,
                                                uint32_t b0, uint32_t b1) {
    asm volatile(
        "mma.sync.aligned.m16n8k16.row.col.f32.bf16.bf16.f32 "
        "{%0,%1,%2,%3}, {%4,%5,%6,%7}, {%8,%9}, {%0,%1,%2,%3};"
        : "+f"(d[0]), "+f"(d[1]), "+f"(d[2]), "+f"(d[3])
        : "r"(a[0]), "r"(a[1]), "r"(a[2]), "r"(a[3]), "r"(b0), "r"(b1));
}
static __device__ __forceinline__ uint32_t pack_bf16x2(float lo, float hi) {
    uint32_t d;
    asm("cvt.rn.bf16x2.f32 %0, %1, %2;" : "=r"(d) : "f"(hi), "f"(lo));
    return d;
}

// ============================================================================
// Pre-pass: split fp32 -> bf16 hi/lo (row-preserving)
// ============================================================================
__global__ __launch_bounds__(256) void split_rows(
    const float* __restrict__ in, __nv_bfloat16* __restrict__ hi,
    __nv_bfloat16* __restrict__ lo, int n4)
{
    int i = blockIdx.x * 256 + threadIdx.x;
    if (i >= n4) return;
    float4 v = ((const float4*)in)[i];
    float a[4] = {v.x, v.y, v.z, v.w};
    __nv_bfloat16 h[4], l[4];
#pragma unroll
    for (int j = 0; j < 4; j++) {
        h[j] = __float2bfloat16(a[j]);
        l[j] = __float2bfloat16(a[j] - __bfloat162float(h[j]));
    }
    __nv_bfloat162* hp = (__nv_bfloat162*)(hi + (size_t)i * 4);
    __nv_bfloat162* lp = (__nv_bfloat162*)(lo + (size_t)i * 4);
    hp[0] = __nv_bfloat162(h[0], h[1]);
    hp[1] = __nv_bfloat162(h[2], h[3]);
    lp[0] = __nv_bfloat162(l[0], l[1]);
    lp[1] = __nv_bfloat162(l[2], l[3]);
}

// ============================================================================
// Pre-pass: W [K,N] fp32 -> W^T [N,K] bf16 hi/lo (tiled transpose)
// ============================================================================
__global__ __launch_bounds__(256) void split_transpose(
    const float* __restrict__ W, __nv_bfloat16* __restrict__ Thi,
    __nv_bfloat16* __restrict__ Tlo)
{
    __shared__ float ts[32][33];
    int tx = threadIdx.x, ty = threadIdx.y;   // 32 x 8
    int x = blockIdx.x * 32 + tx;
#pragma unroll
    for (int i = 0; i < 4; i++)
        ts[ty + i * 8][tx] = W[(size_t)(blockIdx.y * 32 + ty + i * 8) * DMODEL + x];
    __syncthreads();
    int ox = blockIdx.y * 32 + tx;
#pragma unroll
    for (int i = 0; i < 4; i++) {
        float a = ts[tx][ty + i * 8];
        __nv_bfloat16 h = __float2bfloat16(a);
        size_t idx = (size_t)(blockIdx.x * 32 + ty + i * 8) * DMODEL + ox;
        Thi[idx] = h;
        Tlo[idx] = __float2bfloat16(a - __bfloat162float(h));
    }
}

// ============================================================================
// Fused L2-normalize (+scale) and bf16 hi/lo split for Q and K in one launch.
// gridDim.y = 2: y==0 -> Q (scale=SCALE), y==1 -> K (scale=1).
// ============================================================================
__global__ __launch_bounds__(256) void l2norm_split2(
    const float* __restrict__ Qf, const float* __restrict__ Kf,
    __nv_bfloat16* __restrict__ qhi, __nv_bfloat16* __restrict__ qlo,
    __nv_bfloat16* __restrict__ khi, __nv_bfloat16* __restrict__ klo)
{
    int warp = (blockIdx.x * blockDim.x + threadIdx.x) >> 5;
    int lane = threadIdx.x & 31;
    if (warp >= N_TOK * HEADS) return;
    const float* X;
    __nv_bfloat16 *hi, *lo;
    float scale;
    if (blockIdx.y == 0) { X = Qf; hi = qhi; lo = qlo; scale = 8.0f; }
    else                 { X = Kf; hi = khi; lo = klo; scale = 1.0f; }
    size_t base = (size_t)(warp / HEADS) * DMODEL + (warp % HEADS) * DH;
    const float* p = X + base;
    float a = p[lane];
    float b = p[lane + 32];
    float ss = a * a + b * b;
#pragma unroll
    for (int off = 16; off > 0; off >>= 1)
        ss += __shfl_xor_sync(0xffffffffu, ss, off);
    float inv = scale / fmaxf(sqrtf(ss), 1e-12f);
    a *= inv; b *= inv;
    __nv_bfloat16 ah = __float2bfloat16(a), bh = __float2bfloat16(b);
    hi[base + lane]      = ah;
    hi[base + lane + 32] = bh;
    lo[base + lane]      = __float2bfloat16(a - __bfloat162float(ah));
    lo[base + lane + 32] = __float2bfloat16(b - __bfloat162float(bh));
}

// ============================================================================
// Tensor-core GEMM via mma.sync (base ISA): C[M,N] = A @ B^T
// Single __syncthreads per K-stage (prefetch issued after barrier).
// ============================================================================
#define KC 32
#define KP 40
#define TB (128 * KP * 2)              // bytes per tensor tile: 10240
#define OFF_AH 0
#define OFF_AL (TB)
#define OFF_BH (2 * TB)
#define OFF_BL (3 * TB)
#define STAGE_B (4 * TB)               // 40960
#define GEMM_SMEM (2 * STAGE_B)        // 81920

__global__ __launch_bounds__(256) void gemm_tc(
    const __nv_bfloat16* __restrict__ Ahi, const __nv_bfloat16* __restrict__ Alo,
    const __nv_bfloat16* __restrict__ Bhi, const __nv_bfloat16* __restrict__ Blo,
    float* __restrict__ C)
{
    extern __shared__ char smem[];
    const uint32_t sbase = smem_u32(smem);
    const int tid  = threadIdx.x;
    const int lane = tid & 31, warp = tid >> 5;
    const int wm = warp >> 2, wn = warp & 3;          // 2 x 4 warp grid
    const int m0 = blockIdx.y * 128, n0 = blockIdx.x * 128;

    const int lrow0 = tid >> 1;
    const int lsg0  = (tid & 1) * 2;

    float acc[4][4][4];
#pragma unroll
    for (int i = 0; i < 4; i++)
#pragma unroll
        for (int j = 0; j < 4; j++)
#pragma unroll
            for (int r = 0; r < 4; r++) acc[i][j][r] = 0.0f;

    const int NSTG = DMODEL / KC;

    // ---- stage 0 prefetch ----
#pragma unroll
    for (int q = 0; q < 2; q++) {
        int sg = lsg0 + q;
        uint32_t so = (uint32_t)(lrow0 * KP * 2 + sg * 16);
        size_t ga = (size_t)(m0 + lrow0) * DMODEL + sg * 8;
        size_t gb = (size_t)(n0 + lrow0) * DMODEL + sg * 8;
        cp_async16(sbase + OFF_AH + so, Ahi + ga);
        cp_async16(sbase + OFF_AL + so, Alo + ga);
        cp_async16(sbase + OFF_BH + so, Bhi + gb);
        cp_async16(sbase + OFF_BL + so, Blo + gb);
    }
    CP_COMMIT();

    const uint32_t a_r = (uint32_t)((lane & 15));
    const uint32_t a_c = (uint32_t)(((lane >> 4) << 3));
    const uint32_t b_r = (uint32_t)((lane & 7) + ((lane >> 4) << 3));
    const uint32_t b_c = (uint32_t)((((lane >> 3) & 1) << 3));

    for (int s = 0; s < NSTG; s++) {
        CP_WAIT(0);
        __syncthreads();

        if (s + 1 < NSTG) {   // prefetch next stage (buffer reads done pre-barrier)
            const int k0 = (s + 1) * KC;
            const uint32_t nb = sbase + ((s + 1) & 1) * STAGE_B;
#pragma unroll
            for (int q = 0; q < 2; q++) {
                int sg = lsg0 + q;
                uint32_t so = (uint32_t)(lrow0 * KP * 2 + sg * 16);
                size_t ga = (size_t)(m0 + lrow0) * DMODEL + k0 + sg * 8;
                size_t gb = (size_t)(n0 + lrow0) * DMODEL + k0 + sg * 8;
                cp_async16(nb + OFF_AH + so, Ahi + ga);
                cp_async16(nb + OFF_AL + so, Alo + ga);
                cp_async16(nb + OFF_BH + so, Bhi + gb);
                cp_async16(nb + OFF_BL + so, Blo + gb);
            }
            CP_COMMIT();
        }

        const uint32_t bb = sbase + (s & 1) * STAGE_B;
#pragma unroll
        for (int ks = 0; ks < 2; ks++) {
            uint32_t ah[4][4], al[4][4], bh[2][4], bl[2][4];
            const uint32_t acol = (uint32_t)(ks * 16) + a_c;
            const uint32_t bcol = (uint32_t)(ks * 16) + b_c;
#pragma unroll
            for (int i = 0; i < 4; i++) {
                uint32_t off = ((uint32_t)(wm * 64 + i * 16) + a_r) * (KP * 2) + acol * 2;
                ldsm_x4(ah[i], bb + OFF_AH + off);
                ldsm_x4(al[i], bb + OFF_AL + off);
            }
#pragma unroll
            for (int j2 = 0; j2 < 2; j2++) {
                uint32_t off = ((uint32_t)(wn * 32 + j2 * 16) + b_r) * (KP * 2) + bcol * 2;
                ldsm_x4(bh[j2], bb + OFF_BH + off);
                ldsm_x4(bl[j2], bb + OFF_BL + off);
            }
#pragma unroll
            for (int i = 0; i < 4; i++)
#pragma unroll
                for (int j = 0; j < 4; j++) {
                    int j2 = j >> 1, jr = (j & 1) * 2;
                    mma_bf16(acc[i][j], ah[i], bh[j2][jr], bh[j2][jr + 1]);
                    mma_bf16(acc[i][j], ah[i], bl[j2][jr], bl[j2][jr + 1]);
                    mma_bf16(acc[i][j], al[i], bh[j2][jr], bh[j2][jr + 1]);
                }
        }
    }

    const int gq = lane >> 2, tq = lane & 3;
#pragma unroll
    for (int i = 0; i < 4; i++) {
        int row = m0 + wm * 64 + i * 16 + gq;
#pragma unroll
        for (int j = 0; j < 4; j++) {
            int col = n0 + wn * 32 + j * 8 + tq * 2;
            *(float2*)&C[(size_t)row * DMODEL + col] =
                make_float2(acc[i][j][0], acc[i][j][1]);
            *(float2*)&C[(size_t)(row + 8) * DMODEL + col] =
                make_float2(acc[i][j][2], acc[i][j][3]);
        }
    }
}

// ============================================================================
// Tensor-core flash attention (causal), 3-term bf16 split everywhere.
// CTA: 64 queries x one head, 4 warps, 128 threads. Single sync per kb.
// Epilogue writes bf16 hi/lo directly (feeds the Wo GEMM — no fp32 pass).
// ============================================================================
#define FKP 72
#define FTB (64 * FKP * 2)            // 9216 bytes per tile
#define F_QH 0
#define F_QL FTB
#define F_ST (2 * FTB)                // stage region start
#define F_SS (4 * FTB)                // stage stride (kh,kl,vh,vl)
#define F_KH 0
#define F_KL FTB
#define F_VH (2 * FTB)
#define F_VL (3 * FTB)
#define FLASH_SMEM (2 * FTB + 2 * F_SS)   // 92160

__global__ __launch_bounds__(128) void flash_tc(
    const __nv_bfloat16* __restrict__ Qhi, const __nv_bfloat16* __restrict__ Qlo,
    const __nv_bfloat16* __restrict__ Khi, const __nv_bfloat16* __restrict__ Klo,
    const __nv_bfloat16* __restrict__ Vhi, const __nv_bfloat16* __restrict__ Vlo,
    __nv_bfloat16* __restrict__ Ohi, __nv_bfloat16* __restrict__ Olo)
{
    extern __shared__ char smem[];
    const uint32_t sbase = smem_u32(smem);
    const int tid = threadIdx.x;
    const int lane = tid & 31, w = tid >> 5;
    const int qi = gridDim.x - 1 - blockIdx.x;      // heavy blocks first
    const int qs = qi * 64;
    const int hoff = blockIdx.y * DH;

    const int lrow = tid >> 1;
    const int lsg0 = (tid & 1) * 4;

    // ---- Q + stage0 prefetch ----
#pragma unroll
    for (int q = 0; q < 4; q++) {
        int sg = lsg0 + q;
        uint32_t so = (uint32_t)(lrow * FKP * 2 + sg * 16);
        size_t gq = (size_t)(qs + lrow) * DMODEL + hoff + sg * 8;
        cp_async16(sbase + F_QH + so, Qhi + gq);
        cp_async16(sbase + F_QL + so, Qlo + gq);
        size_t gk = (size_t)lrow * DMODEL + hoff + sg * 8;   // key tile 0
        cp_async16(sbase + F_ST + F_KH + so, Khi + gk);
        cp_async16(sbase + F_ST + F_KL + so, Klo + gk);
        cp_async16(sbase + F_ST + F_VH + so, Vhi + gk);
        cp_async16(sbase + F_ST + F_VL + so, Vlo + gk);
    }
    CP_COMMIT();

    const uint32_t a_r = (uint32_t)(lane & 15);
    const uint32_t a_c = (uint32_t)((lane >> 4) << 3);
    const uint32_t b_r = (uint32_t)((lane & 7) + ((lane >> 4) << 3));
    const uint32_t b_c = (uint32_t)(((lane >> 3) & 1) << 3);
    const uint32_t v_r = (uint32_t)((lane & 7) + (((lane >> 3) & 1) << 3));
    const uint32_t v_c = (uint32_t)((lane >> 4) << 3);

    uint32_t qfh[4][4], qfl[4][4];
    float o[8][4];
#pragma unroll
    for (int t = 0; t < 8; t++)
#pragma unroll
        for (int r = 0; r < 4; r++) o[t][r] = 0.0f;
    float m0 = -3.0e38f, m1 = -3.0e38f, l0 = 0.0f, l1 = 0.0f;

    for (int kb = 0; kb <= qi; kb++) {
        CP_WAIT(0);
        __syncthreads();

        if (kb < qi) {   // prefetch next K/V stage (safe post-barrier)
            const uint32_t nb = sbase + F_ST + ((kb + 1) & 1) * F_SS;
            const size_t kt = (size_t)((kb + 1) * 64);
#pragma unroll
            for (int q = 0; q < 4; q++) {
                int sg = lsg0 + q;
                uint32_t so = (uint32_t)(lrow * FKP * 2 + sg * 16);
                size_t gk = (kt + lrow) * DMODEL + hoff + sg * 8;
                cp_async16(nb + F_KH + so, Khi + gk);
                cp_async16(nb + F_KL + so, Klo + gk);
                cp_async16(nb + F_VH + so, Vhi + gk);
                cp_async16(nb + F_VL + so, Vlo + gk);
            }
            CP_COMMIT();
        }

        if (kb == 0) {   // Q fragments (once)
#pragma unroll
            for (int ks = 0; ks < 4; ks++) {
                uint32_t off = ((uint32_t)(w * 16) + a_r) * (FKP * 2)
                             + ((uint32_t)(ks * 16) + a_c) * 2;
                ldsm_x4(qfh[ks], sbase + F_QH + off);
                ldsm_x4(qfl[ks], sbase + F_QL + off);
            }
        }

        const uint32_t bb = sbase + F_ST + (kb & 1) * F_SS;

        // ---- S = Q K^T (3-term) ----
        float sacc[8][4];
#pragma unroll
        for (int t = 0; t < 8; t++)
#pragma unroll
            for (int r = 0; r < 4; r++) sacc[t][r] = 0.0f;
#pragma unroll
        for (int ks = 0; ks < 4; ks++) {
#pragma unroll
            for (int p = 0; p < 4; p++) {
                uint32_t kh4[4], kl4[4];
                uint32_t off = ((uint32_t)(p * 16) + b_r) * (FKP * 2)
                             + ((uint32_t)(ks * 16) + b_c) * 2;
                ldsm_x4(kh4, bb + F_KH + off);
                ldsm_x4(kl4, bb + F_KL + off);
                mma_bf16(sacc[2 * p],     qfh[ks], kh4[0], kh4[1]);
                mma_bf16(sacc[2 * p + 1], qfh[ks], kh4[2], kh4[3]);
                mma_bf16(sacc[2 * p],     qfh[ks], kl4[0], kl4[1]);
                mma_bf16(sacc[2 * p + 1], qfh[ks], kl4[2], kl4[3]);
                mma_bf16(sacc[2 * p],     qfl[ks], kh4[0], kh4[1]);
                mma_bf16(sacc[2 * p + 1], qfl[ks], kh4[2], kh4[3]);
            }
        }

        // ---- causal mask on diagonal tile ----
        const int q0 = w * 16 + (lane >> 2), q1 = q0 + 8;
        if (kb == qi) {
#pragma unroll
            for (int t = 0; t < 8; t++) {
                int k0 = t * 8 + 2 * (lane & 3);
                if (k0     > q0) sacc[t][0] = -3.0e38f;
                if (k0 + 1 > q0) sacc[t][1] = -3.0e38f;
                if (k0     > q1) sacc[t][2] = -3.0e38f;
                if (k0 + 1 > q1) sacc[t][3] = -3.0e38f;
            }
        }

        // ---- online softmax (two rows per lane) ----
        float mx0 = -3.0e38f, mx1 = -3.0e38f;
#pragma unroll
        for (int t = 0; t < 8; t++) {
            mx0 = fmaxf(mx0, fmaxf(sacc[t][0], sacc[t][1]));
            mx1 = fmaxf(mx1, fmaxf(sacc[t][2], sacc[t][3]));
        }
        mx0 = fmaxf(mx0, __shfl_xor_sync(0xffffffffu, mx0, 1));
        mx0 = fmaxf(mx0, __shfl_xor_sync(0xffffffffu, mx0, 2));
        mx1 = fmaxf(mx1, __shfl_xor_sync(0xffffffffu, mx1, 1));
        mx1 = fmaxf(mx1, __shfl_xor_sync(0xffffffffu, mx1, 2));
        float mn0 = fmaxf(m0, mx0), mn1 = fmaxf(m1, mx1);
        float al0 = __expf(m0 - mn0), al1 = __expf(m1 - mn1);
        m0 = mn0; m1 = mn1;
        float rs0 = 0.0f, rs1 = 0.0f;
#pragma unroll
        for (int t = 0; t < 8; t++) {
            sacc[t][0] = __expf(sacc[t][0] - mn0);
            sacc[t][1] = __expf(sacc[t][1] - mn0);
            sacc[t][2] = __expf(sacc[t][2] - mn1);
            sacc[t][3] = __expf(sacc[t][3] - mn1);
            rs0 += sacc[t][0] + sacc[t][1];
            rs1 += sacc[t][2] + sacc[t][3];
        }
        rs0 += __shfl_xor_sync(0xffffffffu, rs0, 1);
        rs0 += __shfl_xor_sync(0xffffffffu, rs0, 2);
        rs1 += __shfl_xor_sync(0xffffffffu, rs1, 1);
        rs1 += __shfl_xor_sync(0xffffffffu, rs1, 2);
        l0 = l0 * al0 + rs0;
        l1 = l1 * al1 + rs1;
#pragma unroll
        for (int t = 0; t < 8; t++) {
            o[t][0] *= al0; o[t][1] *= al0;
            o[t][2] *= al1; o[t][3] *= al1;
        }

        // ---- O += P V (3-term, P split in-register) ----
#pragma unroll
        for (int kc = 0; kc < 4; kc++) {
            float pv[8] = { sacc[2 * kc][0],     sacc[2 * kc][1],
                            sacc[2 * kc][2],     sacc[2 * kc][3],
                            sacc[2 * kc + 1][0], sacc[2 * kc + 1][1],
                            sacc[2 * kc + 1][2], sacc[2 * kc + 1][3] };
            uint32_t aph[4], apl[4];
#pragma unroll
            for (int h = 0; h < 4; h++) {
                float e0 = pv[2 * h], e1 = pv[2 * h + 1];
                float h0 = __bfloat162float(__float2bfloat16(e0));
                float h1 = __bfloat162float(__float2bfloat16(e1));
                aph[h] = pack_bf16x2(h0, h1);
                apl[h] = pack_bf16x2(e0 - h0, e1 - h1);
            }
#pragma unroll
            for (int dp = 0; dp < 4; dp++) {
                uint32_t vh4[4], vl4[4];
                uint32_t off = ((uint32_t)(kc * 16) + v_r) * (FKP * 2)
                             + ((uint32_t)(dp * 16) + v_c) * 2;
                ldsm_x4_t(vh4, bb + F_VH + off);
                ldsm_x4_t(vl4, bb + F_VL + off);
                mma_bf16(o[2 * dp],     aph, vh4[0], vh4[1]);
                mma_bf16(o[2 * dp + 1], aph, vh4[2], vh4[3]);
                mma_bf16(o[2 * dp],     aph, vl4[0], vl4[1]);
                mma_bf16(o[2 * dp + 1], aph, vl4[2], vl4[3]);
                mma_bf16(o[2 * dp],     apl, vh4[0], vh4[1]);
                mma_bf16(o[2 * dp + 1], apl, vh4[2], vh4[3]);
            }
        }
    }

    // ---- epilogue: scale by 1/l, write bf16 hi/lo directly ----
    float inv0 = 1.0f / l0, inv1 = 1.0f / l1;
    int r0 = qs + w * 16 + (lane >> 2);
#pragma unroll
    for (int t = 0; t < 8; t++) {
        int col = hoff + t * 8 + 2 * (lane & 3);
        float a0 = o[t][0] * inv0, a1 = o[t][1] * inv0;
        float b0 = o[t][2] * inv1, b1 = o[t][3] * inv1;
        float ah0 = __bfloat162float(__float2bfloat16(a0));
        float ah1 = __bfloat162float(__float2bfloat16(a1));
        float bh0 = __bfloat162float(__float2bfloat16(b0));
        float bh1 = __bfloat162float(__float2bfloat16(b1));
        size_t i0 = (size_t)r0 * DMODEL + col;
        size_t i1 = (size_t)(r0 + 8) * DMODEL + col;
        *(uint32_t*)&Ohi[i0] = pack_bf16x2(ah0, ah1);
        *(uint32_t*)&Olo[i0] = pack_bf16x2(a0 - ah0, a1 - ah1);
        *(uint32_t*)&Ohi[i1] = pack_bf16x2(bh0, bh1);
        *(uint32_t*)&Olo[i1] = pack_bf16x2(b0 - bh0, b1 - bh1);
    }
}

// ============================================================================
extern "C" void kernel_launch(void* const* d_in, const int* in_sizes, int n_in,
                              void* d_out, int out_size)
{
    const float* x  = (const float*)d_in[0];
    const float* Wq = (const float*)d_in[1];
    const float* Wk = (const float*)d_in[2];
    const float* Wv = (const float*)d_in[3];
    const float* Wo = (const float*)d_in[4];
    float* out = (float*)d_out;

    float *Qp, *Kp, *Vp;
    __nv_bfloat16 *xhi, *xlo, *qhi, *qlo, *khi, *klo, *vhi, *vlo, *ohi, *olo,
                  *wthi, *wtlo;
    cudaGetSymbolAddress((void**)&Qp,  g_Q);
    cudaGetSymbolAddress((void**)&Kp,  g_K);
    cudaGetSymbolAddress((void**)&Vp,  g_V);
    cudaGetSymbolAddress((void**)&xhi, g_xhi);
    cudaGetSymbolAddress((void**)&xlo, g_xlo);
    cudaGetSymbolAddress((void**)&qhi, g_Qhi);
    cudaGetSymbolAddress((void**)&qlo, g_Qlo);
    cudaGetSymbolAddress((void**)&khi, g_Khi);
    cudaGetSymbolAddress((void**)&klo, g_Klo);
    cudaGetSymbolAddress((void**)&vhi, g_Vhi);
    cudaGetSymbolAddress((void**)&vlo, g_Vlo);
    cudaGetSymbolAddress((void**)&ohi, g_Ohi);
    cudaGetSymbolAddress((void**)&olo, g_Olo);
    cudaGetSymbolAddress((void**)&wthi, g_Wthi);
    cudaGetSymbolAddress((void**)&wtlo, g_Wtlo);

    cudaFuncSetAttribute(gemm_tc, cudaFuncAttributeMaxDynamicSharedMemorySize,
                         GEMM_SMEM);
    cudaFuncSetAttribute(flash_tc, cudaFuncAttributeMaxDynamicSharedMemorySize,
                         FLASH_SMEM);

    const size_t WSZ = (size_t)DMODEL * DMODEL;
    const int n4 = N_TOK * DMODEL / 4;

    split_rows<<<(n4 + 255) / 256, 256>>>(x, xhi, xlo, n4);

    dim3 tb(32, 8), tg(DMODEL / 32, DMODEL / 32);
    split_transpose<<<tg, tb>>>(Wq, wthi + 0 * WSZ, wtlo + 0 * WSZ);
    split_transpose<<<tg, tb>>>(Wk, wthi + 1 * WSZ, wtlo + 1 * WSZ);
    split_transpose<<<tg, tb>>>(Wv, wthi + 2 * WSZ, wtlo + 2 * WSZ);
    split_transpose<<<tg, tb>>>(Wo, wthi + 3 * WSZ, wtlo + 3 * WSZ);

    dim3 gg(DMODEL / 128, N_TOK / 128);   // (8, 32)
    gemm_tc<<<gg, 256, GEMM_SMEM>>>(xhi, xlo, wthi + 0 * WSZ, wtlo + 0 * WSZ, Qp);
    gemm_tc<<<gg, 256, GEMM_SMEM>>>(xhi, xlo, wthi + 1 * WSZ, wtlo + 1 * WSZ, Kp);
    gemm_tc<<<gg, 256, GEMM_SMEM>>>(xhi, xlo, wthi + 2 * WSZ, wtlo + 2 * WSZ, Vp);

    int norm_blocks = (N_TOK * HEADS) / 8;
    dim3 ng(norm_blocks, 2);
    l2norm_split2<<<ng, 256>>>(Qp, Kp, qhi, qlo, khi, klo);
    split_rows<<<(n4 + 255) / 256, 256>>>(Vp, vhi, vlo, n4);

    dim3 fa_grid(N_TOK / 64, HEADS);
    flash_tc<<<fa_grid, 128, FLASH_SMEM>>>(qhi, qlo, khi, klo, vhi, vlo, ohi, olo);

    gemm_tc<<<gg, 256, GEMM_SMEM>>>(ohi, olo, wthi + 3 * WSZ, wtlo + 3 * WSZ, out);
}

// round 16
// speedup vs baseline: 2.6930x; 1.0313x over previous
#include <cuda_runtime.h>
#include <cuda_bf16.h>
#include <math.h>
#include <stdint.h>

#define N_TOK  4096
#define DMODEL 1024
#define HEADS  16
#define DH     64

// ---- scratch (no allocations allowed) ----
__device__ __nv_bfloat16 g_xhi[N_TOK * DMODEL];
__device__ __nv_bfloat16 g_xlo[N_TOK * DMODEL];
__device__ __nv_bfloat16 g_Qhi[N_TOK * DMODEL];
__device__ __nv_bfloat16 g_Qlo[N_TOK * DMODEL];
__device__ __nv_bfloat16 g_Khi[N_TOK * DMODEL];
__device__ __nv_bfloat16 g_Klo[N_TOK * DMODEL];
__device__ __nv_bfloat16 g_Vhi[N_TOK * DMODEL];
__device__ __nv_bfloat16 g_Vlo[N_TOK * DMODEL];
__device__ __nv_bfloat16 g_Ohi[N_TOK * DMODEL];
__device__ __nv_bfloat16 g_Olo[N_TOK * DMODEL];
__device__ __nv_bfloat16 g_Wthi[4][DMODEL * DMODEL];   // W^T, bf16 hi
__device__ __nv_bfloat16 g_Wtlo[4][DMODEL * DMODEL];   // W^T, bf16 lo

// ============================================================================
// Base-ISA helpers (NO tcgen05 — ptxas here targets plain sm_103)
// ============================================================================
static __device__ __forceinline__ uint32_t smem_u32(const void* p) {
    uint32_t a;
    asm("{ .reg .u64 t; cvta.to.shared.u64 t, %1; cvt.u32.u64 %0, t; }"
        : "=r"(a) : "l"(p));
    return a;
}
static __device__ __forceinline__ void cp_async16(uint32_t saddr, const void* gaddr) {
    asm volatile("cp.async.cg.shared.global [%0], [%1], 16;"
                 :: "r"(saddr), "l"(gaddr) : "memory");
}
#define CP_COMMIT() asm volatile("cp.async.commit_group;" ::: "memory")
#define CP_WAIT(n)  asm volatile("cp.async.wait_group %0;" :: "n"(n) : "memory")

static __device__ __forceinline__ void ldsm_x4(uint32_t* r, uint32_t addr) {
    asm volatile("ldmatrix.sync.aligned.m8n8.x4.shared.b16 {%0,%1,%2,%3}, [%4];"
                 : "=r"(r[0]), "=r"(r[1]), "=r"(r[2]), "=r"(r[3]) : "r"(addr));
}
static __device__ __forceinline__ void ldsm_x4_t(uint32_t* r, uint32_t addr) {
    asm volatile("ldmatrix.sync.aligned.m8n8.x4.trans.shared.b16 {%0,%1,%2,%3}, [%4];"
                 : "=r"(r[0]), "=r"(r[1]), "=r"(r[2]), "=r"(r[3]) : "r"(addr));
}
static __device__ __forceinline__ void mma_bf16(float* d, const uint32_t* a,
                                                uint32_t b0, uint32_t b1) {
    asm volatile(
        "mma.sync.aligned.m16n8k16.row.col.f32.bf16.bf16.f32 "
        "{%0,%1,%2,%3}, {%4,%5,%6,%7}, {%8,%9}, {%0,%1,%2,%3};"
        : "+f"(d[0]), "+f"(d[1]), "+f"(d[2]), "+f"(d[3])
        : "r"(a[0]), "r"(a[1]), "r"(a[2]), "r"(a[3]), "r"(b0), "r"(b1));
}
static __device__ __forceinline__ uint32_t pack_bf16x2(float lo, float hi) {
    uint32_t d;
    asm("cvt.rn.bf16x2.f32 %0, %1, %2;" : "=r"(d) : "f"(hi), "f"(lo));
    return d;
}

// ============================================================================
// Pre-pass: split fp32 -> bf16 hi/lo (row-preserving)
// ============================================================================
__global__ __launch_bounds__(256) void split_rows(
    const float* __restrict__ in, __nv_bfloat16* __restrict__ hi,
    __nv_bfloat16* __restrict__ lo, int n4)
{
    int i = blockIdx.x * 256 + threadIdx.x;
    if (i >= n4) return;
    float4 v = ((const float4*)in)[i];
    float a[4] = {v.x, v.y, v.z, v.w};
    __nv_bfloat16 h[4], l[4];
#pragma unroll
    for (int j = 0; j < 4; j++) {
        h[j] = __float2bfloat16(a[j]);
        l[j] = __float2bfloat16(a[j] - __bfloat162float(h[j]));
    }
    __nv_bfloat162* hp = (__nv_bfloat162*)(hi + (size_t)i * 4);
    __nv_bfloat162* lp = (__nv_bfloat162*)(lo + (size_t)i * 4);
    hp[0] = __nv_bfloat162(h[0], h[1]);
    hp[1] = __nv_bfloat162(h[2], h[3]);
    lp[0] = __nv_bfloat162(l[0], l[1]);
    lp[1] = __nv_bfloat162(l[2], l[3]);
}

// ============================================================================
// Pre-pass: W [K,N] fp32 -> W^T [N,K] bf16 hi/lo; grid.z picks matrix
// ============================================================================
__global__ __launch_bounds__(256) void split_transpose4(
    const float* __restrict__ W0, const float* __restrict__ W1,
    const float* __restrict__ W2, const float* __restrict__ W3,
    __nv_bfloat16* __restrict__ ThiB, __nv_bfloat16* __restrict__ TloB)
{
    __shared__ float ts[32][33];
    const float* W = (blockIdx.z == 0) ? W0 : (blockIdx.z == 1) ? W1
                   : (blockIdx.z == 2) ? W2 : W3;
    __nv_bfloat16* Thi = ThiB + (size_t)blockIdx.z * DMODEL * DMODEL;
    __nv_bfloat16* Tlo = TloB + (size_t)blockIdx.z * DMODEL * DMODEL;
    int tx = threadIdx.x, ty = threadIdx.y;   // 32 x 8
    int x = blockIdx.x * 32 + tx;
#pragma unroll
    for (int i = 0; i < 4; i++)
        ts[ty + i * 8][tx] = W[(size_t)(blockIdx.y * 32 + ty + i * 8) * DMODEL + x];
    __syncthreads();
    int ox = blockIdx.y * 32 + tx;
#pragma unroll
    for (int i = 0; i < 4; i++) {
        float a = ts[tx][ty + i * 8];
        __nv_bfloat16 h = __float2bfloat16(a);
        size_t idx = (size_t)(blockIdx.x * 32 + ty + i * 8) * DMODEL + ox;
        Thi[idx] = h;
        Tlo[idx] = __float2bfloat16(a - __bfloat162float(h));
    }
}

// ============================================================================
// Shared GEMM mainloop: acc[4][4][4] += A[128xK] @ B^T tile (3-term bf16)
// ============================================================================
#define KC 32
#define KP 40
#define TB (128 * KP * 2)              // bytes per tensor tile: 10240
#define OFF_AH 0
#define OFF_AL (TB)
#define OFF_BH (2 * TB)
#define OFF_BL (3 * TB)
#define STAGE_B (4 * TB)               // 40960
#define GEMM_SMEM (2 * STAGE_B)        // 81920

static __device__ __forceinline__ void gemm_mainloop(
    uint32_t sbase, int tid,
    const __nv_bfloat16* __restrict__ Ahi, const __nv_bfloat16* __restrict__ Alo,
    const __nv_bfloat16* __restrict__ Bhi, const __nv_bfloat16* __restrict__ Blo,
    int m0, int n0, float acc[4][4][4])
{
    const int lane = tid & 31, warp = tid >> 5;
    const int wm = warp >> 2, wn = warp & 3;
    const int lrow0 = tid >> 1;
    const int lsg0  = (tid & 1) * 2;
    const int NSTG = DMODEL / KC;

#pragma unroll
    for (int q = 0; q < 2; q++) {
        int sg = lsg0 + q;
        uint32_t so = (uint32_t)(lrow0 * KP * 2 + sg * 16);
        size_t ga = (size_t)(m0 + lrow0) * DMODEL + sg * 8;
        size_t gb = (size_t)(n0 + lrow0) * DMODEL + sg * 8;
        cp_async16(sbase + OFF_AH + so, Ahi + ga);
        cp_async16(sbase + OFF_AL + so, Alo + ga);
        cp_async16(sbase + OFF_BH + so, Bhi + gb);
        cp_async16(sbase + OFF_BL + so, Blo + gb);
    }
    CP_COMMIT();

    const uint32_t a_r = (uint32_t)((lane & 15));
    const uint32_t a_c = (uint32_t)(((lane >> 4) << 3));
    const uint32_t b_r = (uint32_t)((lane & 7) + ((lane >> 4) << 3));
    const uint32_t b_c = (uint32_t)((((lane >> 3) & 1) << 3));

    for (int s = 0; s < NSTG; s++) {
        CP_WAIT(0);
        __syncthreads();

        if (s + 1 < NSTG) {
            const int k0 = (s + 1) * KC;
            const uint32_t nb = sbase + ((s + 1) & 1) * STAGE_B;
#pragma unroll
            for (int q = 0; q < 2; q++) {
                int sg = lsg0 + q;
                uint32_t so = (uint32_t)(lrow0 * KP * 2 + sg * 16);
                size_t ga = (size_t)(m0 + lrow0) * DMODEL + k0 + sg * 8;
                size_t gb = (size_t)(n0 + lrow0) * DMODEL + k0 + sg * 8;
                cp_async16(nb + OFF_AH + so, Ahi + ga);
                cp_async16(nb + OFF_AL + so, Alo + ga);
                cp_async16(nb + OFF_BH + so, Bhi + gb);
                cp_async16(nb + OFF_BL + so, Blo + gb);
            }
            CP_COMMIT();
        }

        const uint32_t bb = sbase + (s & 1) * STAGE_B;
#pragma unroll
        for (int ks = 0; ks < 2; ks++) {
            uint32_t ah[4][4], al[4][4], bh[2][4], bl[2][4];
            const uint32_t acol = (uint32_t)(ks * 16) + a_c;
            const uint32_t bcol = (uint32_t)(ks * 16) + b_c;
#pragma unroll
            for (int i = 0; i < 4; i++) {
                uint32_t off = ((uint32_t)(wm * 64 + i * 16) + a_r) * (KP * 2) + acol * 2;
                ldsm_x4(ah[i], bb + OFF_AH + off);
                ldsm_x4(al[i], bb + OFF_AL + off);
            }
#pragma unroll
            for (int j2 = 0; j2 < 2; j2++) {
                uint32_t off = ((uint32_t)(wn * 32 + j2 * 16) + b_r) * (KP * 2) + bcol * 2;
                ldsm_x4(bh[j2], bb + OFF_BH + off);
                ldsm_x4(bl[j2], bb + OFF_BL + off);
            }
#pragma unroll
            for (int i = 0; i < 4; i++)
#pragma unroll
                for (int j = 0; j < 4; j++) {
                    int j2 = j >> 1, jr = (j & 1) * 2;
                    mma_bf16(acc[i][j], ah[i], bh[j2][jr], bh[j2][jr + 1]);
                    mma_bf16(acc[i][j], ah[i], bl[j2][jr], bl[j2][jr + 1]);
                    mma_bf16(acc[i][j], al[i], bh[j2][jr], bh[j2][jr + 1]);
                }
        }
    }
}

// ============================================================================
// QKV GEMM: grid.z = 0(Q) / 1(K) / 2(V).  Fused epilogue:
//   Q/K: per-(row,head) L2 norm (128-col tile = exactly 2 heads) -> bf16 hi/lo
//   V:   plain bf16 hi/lo split
// ============================================================================
__global__ __launch_bounds__(256) void gemm_qkv(
    const __nv_bfloat16* __restrict__ xhi, const __nv_bfloat16* __restrict__ xlo,
    const __nv_bfloat16* __restrict__ WthiB, const __nv_bfloat16* __restrict__ WtloB,
    __nv_bfloat16* __restrict__ qhi, __nv_bfloat16* __restrict__ qlo,
    __nv_bfloat16* __restrict__ khi, __nv_bfloat16* __restrict__ klo,
    __nv_bfloat16* __restrict__ vhi, __nv_bfloat16* __restrict__ vlo)
{
    extern __shared__ char smem[];
    const uint32_t sbase = smem_u32(smem);
    const int tid = threadIdx.x;
    const int z = blockIdx.z;
    const int m0 = blockIdx.y * 128, n0 = blockIdx.x * 128;

    float acc[4][4][4];
#pragma unroll
    for (int i = 0; i < 4; i++)
#pragma unroll
        for (int j = 0; j < 4; j++)
#pragma unroll
            for (int r = 0; r < 4; r++) acc[i][j][r] = 0.0f;

    gemm_mainloop(sbase, tid,
                  xhi, xlo,
                  WthiB + (size_t)z * DMODEL * DMODEL,
                  WtloB + (size_t)z * DMODEL * DMODEL,
                  m0, n0, acc);

    const int lane = tid & 31, warp = tid >> 5;
    const int wm = warp >> 2, wn = warp & 3;
    const int gq = lane >> 2, tq = lane & 3;

    __nv_bfloat16 *hi, *lo;
    if (z == 0)      { hi = qhi; lo = qlo; }
    else if (z == 1) { hi = khi; lo = klo; }
    else             { hi = vhi; lo = vlo; }

    float inv[4][2];   // [i][rowhalf] scaling factor
    if (z < 2) {
        // per-thread partial sum of squares for its 8 row-instances
        float* red = (float*)smem;    // 4 x 128 floats (reuse pipeline smem)
        __syncthreads();              // all ldsm reads of last stage done
        float part[4][2];
#pragma unroll
        for (int i = 0; i < 4; i++)
#pragma unroll
            for (int t = 0; t < 2; t++) {
                float p = 0.0f;
#pragma unroll
                for (int j = 0; j < 4; j++)
                    p += acc[i][j][2 * t] * acc[i][j][2 * t]
                       + acc[i][j][2 * t + 1] * acc[i][j][2 * t + 1];
                p += __shfl_xor_sync(0xffffffffu, p, 1);
                p += __shfl_xor_sync(0xffffffffu, p, 2);
                part[i][t] = p;
            }
        if (tq == 0) {
#pragma unroll
            for (int i = 0; i < 4; i++) {
                red[wn * 128 + wm * 64 + i * 16 + gq]     = part[i][0];
                red[wn * 128 + wm * 64 + i * 16 + gq + 8] = part[i][1];
            }
        }
        __syncthreads();
        const int hb = (wn >> 1) * 2;   // 0 for cols 0-63, 2 for cols 64-127
        const float scale = (z == 0) ? 8.0f : 1.0f;
#pragma unroll
        for (int i = 0; i < 4; i++) {
            int r0 = wm * 64 + i * 16 + gq;
            float ss0 = red[hb * 128 + r0]       + red[(hb + 1) * 128 + r0];
            float ss1 = red[hb * 128 + r0 + 8]   + red[(hb + 1) * 128 + r0 + 8];
            inv[i][0] = scale / fmaxf(sqrtf(ss0), 1e-12f);
            inv[i][1] = scale / fmaxf(sqrtf(ss1), 1e-12f);
        }
    } else {
#pragma unroll
        for (int i = 0; i < 4; i++) { inv[i][0] = 1.0f; inv[i][1] = 1.0f; }
    }

#pragma unroll
    for (int i = 0; i < 4; i++) {
        int row = m0 + wm * 64 + i * 16 + gq;
#pragma unroll
        for (int j = 0; j < 4; j++) {
            int col = n0 + wn * 32 + j * 8 + tq * 2;
            float a0 = acc[i][j][0] * inv[i][0], a1 = acc[i][j][1] * inv[i][0];
            float b0 = acc[i][j][2] * inv[i][1], b1 = acc[i][j][3] * inv[i][1];
            float ah0 = __bfloat162float(__float2bfloat16(a0));
            float ah1 = __bfloat162float(__float2bfloat16(a1));
            float bh0 = __bfloat162float(__float2bfloat16(b0));
            float bh1 = __bfloat162float(__float2bfloat16(b1));
            size_t i0 = (size_t)row * DMODEL + col;
            size_t i1 = (size_t)(row + 8) * DMODEL + col;
            *(uint32_t*)&hi[i0] = pack_bf16x2(ah0, ah1);
            *(uint32_t*)&lo[i0] = pack_bf16x2(a0 - ah0, a1 - ah1);
            *(uint32_t*)&hi[i1] = pack_bf16x2(bh0, bh1);
            *(uint32_t*)&lo[i1] = pack_bf16x2(b0 - bh0, b1 - bh1);
        }
    }
}

// ============================================================================
// Output GEMM (Wo): fp32 epilogue to d_out
// ============================================================================
__global__ __launch_bounds__(256) void gemm_out(
    const __nv_bfloat16* __restrict__ Ahi, const __nv_bfloat16* __restrict__ Alo,
    const __nv_bfloat16* __restrict__ Bhi, const __nv_bfloat16* __restrict__ Blo,
    float* __restrict__ C)
{
    extern __shared__ char smem[];
    const uint32_t sbase = smem_u32(smem);
    const int tid = threadIdx.x;
    const int m0 = blockIdx.y * 128, n0 = blockIdx.x * 128;

    float acc[4][4][4];
#pragma unroll
    for (int i = 0; i < 4; i++)
#pragma unroll
        for (int j = 0; j < 4; j++)
#pragma unroll
            for (int r = 0; r < 4; r++) acc[i][j][r] = 0.0f;

    gemm_mainloop(sbase, tid, Ahi, Alo, Bhi, Blo, m0, n0, acc);

    const int lane = tid & 31, warp = tid >> 5;
    const int wm = warp >> 2, wn = warp & 3;
    const int gq = lane >> 2, tq = lane & 3;
#pragma unroll
    for (int i = 0; i < 4; i++) {
        int row = m0 + wm * 64 + i * 16 + gq;
#pragma unroll
        for (int j = 0; j < 4; j++) {
            int col = n0 + wn * 32 + j * 8 + tq * 2;
            *(float2*)&C[(size_t)row * DMODEL + col] =
                make_float2(acc[i][j][0], acc[i][j][1]);
            *(float2*)&C[(size_t)(row + 8) * DMODEL + col] =
                make_float2(acc[i][j][2], acc[i][j][3]);
        }
    }
}

// ============================================================================
// Tensor-core flash attention (causal), 3-term bf16 split everywhere.
// CTA: 64 queries x one head, 4 warps, 128 threads. Single sync per kb.
// Epilogue writes bf16 hi/lo directly (feeds the Wo GEMM — no fp32 pass).
// ============================================================================
#define FKP 72
#define FTB (64 * FKP * 2)            // 9216 bytes per tile
#define F_QH 0
#define F_QL FTB
#define F_ST (2 * FTB)                // stage region start
#define F_SS (4 * FTB)                // stage stride (kh,kl,vh,vl)
#define F_KH 0
#define F_KL FTB
#define F_VH (2 * FTB)
#define F_VL (3 * FTB)
#define FLASH_SMEM (2 * FTB + 2 * F_SS)   // 92160

__global__ __launch_bounds__(128) void flash_tc(
    const __nv_bfloat16* __restrict__ Qhi, const __nv_bfloat16* __restrict__ Qlo,
    const __nv_bfloat16* __restrict__ Khi, const __nv_bfloat16* __restrict__ Klo,
    const __nv_bfloat16* __restrict__ Vhi, const __nv_bfloat16* __restrict__ Vlo,
    __nv_bfloat16* __restrict__ Ohi, __nv_bfloat16* __restrict__ Olo)
{
    extern __shared__ char smem[];
    const uint32_t sbase = smem_u32(smem);
    const int tid = threadIdx.x;
    const int lane = tid & 31, w = tid >> 5;
    const int qi = gridDim.x - 1 - blockIdx.x;      // heavy blocks first
    const int qs = qi * 64;
    const int hoff = blockIdx.y * DH;

    const int lrow = tid >> 1;
    const int lsg0 = (tid & 1) * 4;

    // ---- Q + stage0 prefetch ----
#pragma unroll
    for (int q = 0; q < 4; q++) {
        int sg = lsg0 + q;
        uint32_t so = (uint32_t)(lrow * FKP * 2 + sg * 16);
        size_t gq = (size_t)(qs + lrow) * DMODEL + hoff + sg * 8;
        cp_async16(sbase + F_QH + so, Qhi + gq);
        cp_async16(sbase + F_QL + so, Qlo + gq);
        size_t gk = (size_t)lrow * DMODEL + hoff + sg * 8;   // key tile 0
        cp_async16(sbase + F_ST + F_KH + so, Khi + gk);
        cp_async16(sbase + F_ST + F_KL + so, Klo + gk);
        cp_async16(sbase + F_ST + F_VH + so, Vhi + gk);
        cp_async16(sbase + F_ST + F_VL + so, Vlo + gk);
    }
    CP_COMMIT();

    const uint32_t a_r = (uint32_t)(lane & 15);
    const uint32_t a_c = (uint32_t)((lane >> 4) << 3);
    const uint32_t b_r = (uint32_t)((lane & 7) + ((lane >> 4) << 3));
    const uint32_t b_c = (uint32_t)(((lane >> 3) & 1) << 3);
    const uint32_t v_r = (uint32_t)((lane & 7) + (((lane >> 3) & 1) << 3));
    const uint32_t v_c = (uint32_t)((lane >> 4) << 3);

    uint32_t qfh[4][4], qfl[4][4];
    float o[8][4];
#pragma unroll
    for (int t = 0; t < 8; t++)
#pragma unroll
        for (int r = 0; r < 4; r++) o[t][r] = 0.0f;
    float m0 = -3.0e38f, m1 = -3.0e38f, l0 = 0.0f, l1 = 0.0f;

    for (int kb = 0; kb <= qi; kb++) {
        CP_WAIT(0);
        __syncthreads();

        if (kb < qi) {   // prefetch next K/V stage (safe post-barrier)
            const uint32_t nb = sbase + F_ST + ((kb + 1) & 1) * F_SS;
            const size_t kt = (size_t)((kb + 1) * 64);
#pragma unroll
            for (int q = 0; q < 4; q++) {
                int sg = lsg0 + q;
                uint32_t so = (uint32_t)(lrow * FKP * 2 + sg * 16);
                size_t gk = (kt + lrow) * DMODEL + hoff + sg * 8;
                cp_async16(nb + F_KH + so, Khi + gk);
                cp_async16(nb + F_KL + so, Klo + gk);
                cp_async16(nb + F_VH + so, Vhi + gk);
                cp_async16(nb + F_VL + so, Vlo + gk);
            }
            CP_COMMIT();
        }

        if (kb == 0) {   // Q fragments (once)
#pragma unroll
            for (int ks = 0; ks < 4; ks++) {
                uint32_t off = ((uint32_t)(w * 16) + a_r) * (FKP * 2)
                             + ((uint32_t)(ks * 16) + a_c) * 2;
                ldsm_x4(qfh[ks], sbase + F_QH + off);
                ldsm_x4(qfl[ks], sbase + F_QL + off);
            }
        }

        const uint32_t bb = sbase + F_ST + (kb & 1) * F_SS;

        // ---- S = Q K^T (3-term) ----
        float sacc[8][4];
#pragma unroll
        for (int t = 0; t < 8; t++)
#pragma unroll
            for (int r = 0; r < 4; r++) sacc[t][r] = 0.0f;
#pragma unroll
        for (int ks = 0; ks < 4; ks++) {
#pragma unroll
            for (int p = 0; p < 4; p++) {
                uint32_t kh4[4], kl4[4];
                uint32_t off = ((uint32_t)(p * 16) + b_r) * (FKP * 2)
                             + ((uint32_t)(ks * 16) + b_c) * 2;
                ldsm_x4(kh4, bb + F_KH + off);
                ldsm_x4(kl4, bb + F_KL + off);
                mma_bf16(sacc[2 * p],     qfh[ks], kh4[0], kh4[1]);
                mma_bf16(sacc[2 * p + 1], qfh[ks], kh4[2], kh4[3]);
                mma_bf16(sacc[2 * p],     qfh[ks], kl4[0], kl4[1]);
                mma_bf16(sacc[2 * p + 1], qfh[ks], kl4[2], kl4[3]);
                mma_bf16(sacc[2 * p],     qfl[ks], kh4[0], kh4[1]);
                mma_bf16(sacc[2 * p + 1], qfl[ks], kh4[2], kh4[3]);
            }
        }

        // ---- causal mask on diagonal tile ----
        const int q0 = w * 16 + (lane >> 2), q1 = q0 + 8;
        if (kb == qi) {
#pragma unroll
            for (int t = 0; t < 8; t++) {
                int k0 = t * 8 + 2 * (lane & 3);
                if (k0     > q0) sacc[t][0] = -3.0e38f;
                if (k0 + 1 > q0) sacc[t][1] = -3.0e38f;
                if (k0     > q1) sacc[t][2] = -3.0e38f;
                if (k0 + 1 > q1) sacc[t][3] = -3.0e38f;
            }
        }

        // ---- online softmax (two rows per lane) ----
        float mx0 = -3.0e38f, mx1 = -3.0e38f;
#pragma unroll
        for (int t = 0; t < 8; t++) {
            mx0 = fmaxf(mx0, fmaxf(sacc[t][0], sacc[t][1]));
            mx1 = fmaxf(mx1, fmaxf(sacc[t][2], sacc[t][3]));
        }
        mx0 = fmaxf(mx0, __shfl_xor_sync(0xffffffffu, mx0, 1));
        mx0 = fmaxf(mx0, __shfl_xor_sync(0xffffffffu, mx0, 2));
        mx1 = fmaxf(mx1, __shfl_xor_sync(0xffffffffu, mx1, 1));
        mx1 = fmaxf(mx1, __shfl_xor_sync(0xffffffffu, mx1, 2));
        float mn0 = fmaxf(m0, mx0), mn1 = fmaxf(m1, mx1);
        float al0 = __expf(m0 - mn0), al1 = __expf(m1 - mn1);
        m0 = mn0; m1 = mn1;
        float rs0 = 0.0f, rs1 = 0.0f;
#pragma unroll
        for (int t = 0; t < 8; t++) {
            sacc[t][0] = __expf(sacc[t][0] - mn0);
            sacc[t][1] = __expf(sacc[t][1] - mn0);
            sacc[t][2] = __expf(sacc[t][2] - mn1);
            sacc[t][3] = __expf(sacc[t][3] - mn1);
            rs0 += sacc[t][0] + sacc[t][1];
            rs1 += sacc[t][2] + sacc[t][3];
        }
        rs0 += __shfl_xor_sync(0xffffffffu, rs0, 1);
        rs0 += __shfl_xor_sync(0xffffffffu, rs0, 2);
        rs1 += __shfl_xor_sync(0xffffffffu, rs1, 1);
        rs1 += __shfl_xor_sync(0xffffffffu, rs1, 2);
        l0 = l0 * al0 + rs0;
        l1 = l1 * al1 + rs1;
#pragma unroll
        for (int t = 0; t < 8; t++) {
            o[t][0] *= al0; o[t][1] *= al0;
            o[t][2] *= al1; o[t][3] *= al1;
        }

        // ---- O += P V (3-term, P split in-register) ----
#pragma unroll
        for (int kc = 0; kc < 4; kc++) {
            float pv[8] = { sacc[2 * kc][0],     sacc[2 * kc][1],
                            sacc[2 * kc][2],     sacc[2 * kc][3],
                            sacc[2 * kc + 1][0], sacc[2 * kc + 1][1],
                            sacc[2 * kc + 1][2], sacc[2 * kc + 1][3] };
            uint32_t aph[4], apl[4];
#pragma unroll
            for (int h = 0; h < 4; h++) {
                float e0 = pv[2 * h], e1 = pv[2 * h + 1];
                float h0 = __bfloat162float(__float2bfloat16(e0));
                float h1 = __bfloat162float(__float2bfloat16(e1));
                aph[h] = pack_bf16x2(h0, h1);
                apl[h] = pack_bf16x2(e0 - h0, e1 - h1);
            }
#pragma unroll
            for (int dp = 0; dp < 4; dp++) {
                uint32_t vh4[4], vl4[4];
                uint32_t off = ((uint32_t)(kc * 16) + v_r) * (FKP * 2)
                             + ((uint32_t)(dp * 16) + v_c) * 2;
                ldsm_x4_t(vh4, bb + F_VH + off);
                ldsm_x4_t(vl4, bb + F_VL + off);
                mma_bf16(o[2 * dp],     aph, vh4[0], vh4[1]);
                mma_bf16(o[2 * dp + 1], aph, vh4[2], vh4[3]);
                mma_bf16(o[2 * dp],     aph, vl4[0], vl4[1]);
                mma_bf16(o[2 * dp + 1], aph, vl4[2], vl4[3]);
                mma_bf16(o[2 * dp],     apl, vh4[0], vh4[1]);
                mma_bf16(o[2 * dp + 1], apl, vh4[2], vh4[3]);
            }
        }
    }

    // ---- epilogue: scale by 1/l, write bf16 hi/lo directly ----
    float inv0 = 1.0f / l0, inv1 = 1.0f / l1;
    int r0 = qs + w * 16 + (lane >> 2);
#pragma unroll
    for (int t = 0; t < 8; t++) {
        int col = hoff + t * 8 + 2 * (lane & 3);
        float a0 = o[t][0] * inv0, a1 = o[t][1] * inv0;
        float b0 = o[t][2] * inv1, b1 = o[t][3] * inv1;
        float ah0 = __bfloat162float(__float2bfloat16(a0));
        float ah1 = __bfloat162float(__float2bfloat16(a1));
        float bh0 = __bfloat162float(__float2bfloat16(b0));
        float bh1 = __bfloat162float(__float2bfloat16(b1));
        size_t i0 = (size_t)r0 * DMODEL + col;
        size_t i1 = (size_t)(r0 + 8) * DMODEL + col;
        *(uint32_t*)&Ohi[i0] = pack_bf16x2(ah0, ah1);
        *(uint32_t*)&Olo[i0] = pack_bf16x2(a0 - ah0, a1 - ah1);
        *(uint32_t*)&Ohi[i1] = pack_bf16x2(bh0, bh1);
        *(uint32_t*)&Olo[i1] = pack_bf16x2(b0 - bh0, b1 - bh1);
    }
}

// ============================================================================
extern "C" void kernel_launch(void* const* d_in, const int* in_sizes, int n_in,
                              void* d_out, int out_size)
{
    const float* x  = (const float*)d_in[0];
    const float* Wq = (const float*)d_in[1];
    const float* Wk = (const float*)d_in[2];
    const float* Wv = (const float*)d_in[3];
    const float* Wo = (const float*)d_in[4];
    float* out = (float*)d_out;

    __nv_bfloat16 *xhi, *xlo, *qhi, *qlo, *khi, *klo, *vhi, *vlo, *ohi, *olo,
                  *wthi, *wtlo;
    cudaGetSymbolAddress((void**)&xhi, g_xhi);
    cudaGetSymbolAddress((void**)&xlo, g_xlo);
    cudaGetSymbolAddress((void**)&qhi, g_Qhi);
    cudaGetSymbolAddress((void**)&qlo, g_Qlo);
    cudaGetSymbolAddress((void**)&khi, g_Khi);
    cudaGetSymbolAddress((void**)&klo, g_Klo);
    cudaGetSymbolAddress((void**)&vhi, g_Vhi);
    cudaGetSymbolAddress((void**)&vlo, g_Vlo);
    cudaGetSymbolAddress((void**)&ohi, g_Ohi);
    cudaGetSymbolAddress((void**)&olo, g_Olo);
    cudaGetSymbolAddress((void**)&wthi, g_Wthi);
    cudaGetSymbolAddress((void**)&wtlo, g_Wtlo);

    cudaFuncSetAttribute(gemm_qkv, cudaFuncAttributeMaxDynamicSharedMemorySize,
                         GEMM_SMEM);
    cudaFuncSetAttribute(gemm_out, cudaFuncAttributeMaxDynamicSharedMemorySize,
                         GEMM_SMEM);
    cudaFuncSetAttribute(flash_tc, cudaFuncAttributeMaxDynamicSharedMemorySize,
                         FLASH_SMEM);

    const size_t WSZ = (size_t)DMODEL * DMODEL;
    const int n4 = N_TOK * DMODEL / 4;

    split_rows<<<(n4 + 255) / 256, 256>>>(x, xhi, xlo, n4);

    dim3 tb(32, 8), tg(DMODEL / 32, DMODEL / 32, 4);
    split_transpose4<<<tg, tb>>>(Wq, Wk, Wv, Wo, wthi, wtlo);

    dim3 gq(DMODEL / 128, N_TOK / 128, 3);   // (8, 32, 3)
    gemm_qkv<<<gq, 256, GEMM_SMEM>>>(xhi, xlo, wthi, wtlo,
                                     qhi, qlo, khi, klo, vhi, vlo);

    dim3 fa_grid(N_TOK / 64, HEADS);
    flash_tc<<<fa_grid, 128, FLASH_SMEM>>>(qhi, qlo, khi, klo, vhi, vlo, ohi, olo);

    dim3 gg(DMODEL / 128, N_TOK / 128);
    gemm_out<<<gg, 256, GEMM_SMEM>>>(ohi, olo, wthi + 3 * WSZ, wtlo + 3 * WSZ, out);
}